// round 12
// baseline (speedup 1.0000x reference)
#include <cuda_runtime.h>
#include <cuda_fp16.h>
#include <cuda_bf16.h>
#include <math.h>
#include <stdint.h>

#define B    2
#define T    2048
#define H    1024
#define NH   16
#define D    64
#define SCALE 0.125f   // D^-0.5

// ---------------- static device scratch (no dynamic allocation allowed) ----
__device__ __nv_bfloat16 g_Qh[(size_t)B * T * H];   // 8 MB
__device__ __nv_bfloat16 g_Kh[(size_t)B * T * H];   // 8 MB
__device__ __half g_Vth[(size_t)B * D * T];         // 0.5 MB V transposed fp16 [b][d][s]
__device__ __half g_Wh[(size_t)NH * B * T * T];     // 268 MB exp(score) fp16
__device__ __half g_MWh[(size_t)B * T * T];         // 16 MB mean_weights fp16 copy
__device__ float  g_RS[(size_t)NH * B * T * 16];    // 4 MB per-(row,s-tile) exp sums
__device__ float  g_MHp[(size_t)8 * B * T * D];     // 8 MB AV partials (8 chunks)
__device__ float  g_MH[(size_t)B * T * D];          // 1 MB reduced mean_head

// ---------------------------------------------------------------------------
__device__ __forceinline__ uint32_t pack_bf2(float lo, float hi) {
    __nv_bfloat162 h = __floats2bfloat162_rn(lo, hi);
    return *(uint32_t*)&h;
}

__device__ __forceinline__ void mma_bf16(float* d, const uint32_t* a, const uint32_t* b) {
    asm volatile(
        "mma.sync.aligned.m16n8k16.row.col.f32.bf16.bf16.f32 "
        "{%0,%1,%2,%3}, {%4,%5,%6,%7}, {%8,%9}, {%0,%1,%2,%3};"
        : "+f"(d[0]), "+f"(d[1]), "+f"(d[2]), "+f"(d[3])
        : "r"(a[0]), "r"(a[1]), "r"(a[2]), "r"(a[3]), "r"(b[0]), "r"(b[1]));
}

__device__ __forceinline__ void mma_fp16(float* d, const uint32_t* a, const uint32_t* b) {
    asm volatile(
        "mma.sync.aligned.m16n8k16.row.col.f32.f16.f16.f32 "
        "{%0,%1,%2,%3}, {%4,%5,%6,%7}, {%8,%9}, {%0,%1,%2,%3};"
        : "+f"(d[0]), "+f"(d[1]), "+f"(d[2]), "+f"(d[3])
        : "r"(a[0]), "r"(a[1]), "r"(a[2]), "r"(a[3]), "r"(b[0]), "r"(b[1]));
}

__device__ __forceinline__ uint32_t smem_u32(const void* p) {
    uint32_t a;
    asm("{ .reg .u64 t; cvta.to.shared.u64 t, %1; cvt.u32.u64 %0, t; }"
        : "=r"(a) : "l"(p));
    return a;
}

__device__ __forceinline__ void ldsm_x4(uint32_t* r, uint32_t addr) {
    asm volatile("ldmatrix.sync.aligned.m8n8.x4.shared.b16 {%0,%1,%2,%3}, [%4];"
        : "=r"(r[0]), "=r"(r[1]), "=r"(r[2]), "=r"(r[3]) : "r"(addr));
}

// ---------------------------------------------------------------------------
// Kernel 1: FUSED Q/K projection (bf16 mma, z=0/1) + V projection (fp32 SIMT,
// z=2, writes transposed fp16 V). grid = (8, 32, 3), 256 threads.
// ---------------------------------------------------------------------------
union ProjSmem {
    struct { uint32_t As2[2][128][20]; uint32_t Bs2[2][16][136]; } qk;
    struct { float As[64][17]; float Bs[16][65]; } v;
};

__global__ void __launch_bounds__(256)
qkvproj_kernel(const float* __restrict__ x,
               const float* __restrict__ Wq, const float* __restrict__ bq,
               const float* __restrict__ Wk, const float* __restrict__ bk,
               const float* __restrict__ Wv, const float* __restrict__ bv)
{
    __shared__ ProjSmem sm;
    const int tid = threadIdx.x;

    // ===================== z == 2 : V projection (SIMT fp32) ===============
    if (blockIdx.z == 2) {
        if (blockIdx.y >= 8) return;
        const int m0 = (blockIdx.y * 8 + blockIdx.x) * 64;
        const int tx = tid & 15, ty = tid >> 4;

        float acc[4][4];
#pragma unroll
        for (int i = 0; i < 4; i++)
#pragma unroll
            for (int j = 0; j < 4; j++) acc[i][j] = 0.f;

        for (int k0 = 0; k0 < H; k0 += 16) {
#pragma unroll
            for (int i = 0; i < 4; i++) {
                int idx = tid + i * 256;
                int r = idx >> 4, c = idx & 15;
                sm.v.As[r][c] = x[(size_t)(m0 + r) * H + k0 + c];
            }
#pragma unroll
            for (int i = 0; i < 4; i++) {
                int idx = tid + i * 256;
                int r = idx >> 6, c = idx & 63;
                sm.v.Bs[r][c] = Wv[(size_t)(k0 + r) * D + c];
            }
            __syncthreads();
#pragma unroll
            for (int kk = 0; kk < 16; kk++) {
                float a[4], bb[4];
#pragma unroll
                for (int i = 0; i < 4; i++) a[i]  = sm.v.As[ty * 4 + i][kk];
#pragma unroll
                for (int j = 0; j < 4; j++) bb[j] = sm.v.Bs[kk][tx * 4 + j];
#pragma unroll
                for (int i = 0; i < 4; i++)
#pragma unroll
                    for (int j = 0; j < 4; j++) acc[i][j] += a[i] * bb[j];
            }
            __syncthreads();
        }
        const int b = m0 >> 11;
        const int tbase = (m0 & 2047) + ty * 4;
#pragma unroll
        for (int i = 0; i < 4; i++)
#pragma unroll
            for (int j = 0; j < 4; j++) {
                const int d = tx * 4 + j;
                g_Vth[((size_t)b * D + d) * T + tbase + i] =
                    __float2half(acc[i][j] + bv[d]);
            }
        return;
    }

    // ===================== z == 0/1 : Q/K projection (bf16 mma) ============
    const float* Wm    = blockIdx.z ? Wk : Wq;
    const float* bias  = blockIdx.z ? bk : bq;
    __nv_bfloat16* C   = blockIdx.z ? g_Kh : g_Qh;
    const int n0 = blockIdx.x * 128;
    const int m0 = blockIdx.y * 128;

    const int lane = tid & 31;
    const int wid  = tid >> 5;
    const int wm   = wid >> 2;
    const int wn   = wid & 3;
    const int fr   = lane >> 2;
    const int fc   = lane & 3;

    const int am = tid >> 1;
    const int ak = (tid & 1) * 16;
    const float* xrow = x + (size_t)(m0 + am) * H + ak;
    const int p  = tid >> 4;
    const int nn = (tid & 15) * 8;
    const int bcol = n0 + nn;
    const size_t bbase = (size_t)(bcol >> 6) * (H * D) + (size_t)(bcol & 63);

    float acc[4][4][4];
#pragma unroll
    for (int i = 0; i < 4; i++)
#pragma unroll
        for (int j = 0; j < 4; j++)
#pragma unroll
            for (int q = 0; q < 4; q++) acc[i][j][q] = 0.f;

    float4 a0, a1, a2, a3, blo0, blo1, bhi0, bhi1;

    a0 = *(const float4*)&xrow[0];
    a1 = *(const float4*)&xrow[4];
    a2 = *(const float4*)&xrow[8];
    a3 = *(const float4*)&xrow[12];
    blo0 = *(const float4*)&Wm[bbase + (size_t)(2 * p)     * D];
    blo1 = *(const float4*)&Wm[bbase + (size_t)(2 * p)     * D + 4];
    bhi0 = *(const float4*)&Wm[bbase + (size_t)(2 * p + 1) * D];
    bhi1 = *(const float4*)&Wm[bbase + (size_t)(2 * p + 1) * D + 4];
    {
        uint4 u;
        u.x = pack_bf2(a0.x, a0.y); u.y = pack_bf2(a0.z, a0.w);
        u.z = pack_bf2(a1.x, a1.y); u.w = pack_bf2(a1.z, a1.w);
        *(uint4*)&sm.qk.As2[0][am][ak / 2] = u;
        u.x = pack_bf2(a2.x, a2.y); u.y = pack_bf2(a2.z, a2.w);
        u.z = pack_bf2(a3.x, a3.y); u.w = pack_bf2(a3.z, a3.w);
        *(uint4*)&sm.qk.As2[0][am][ak / 2 + 4] = u;
        u.x = pack_bf2(blo0.x, bhi0.x); u.y = pack_bf2(blo0.y, bhi0.y);
        u.z = pack_bf2(blo0.z, bhi0.z); u.w = pack_bf2(blo0.w, bhi0.w);
        *(uint4*)&sm.qk.Bs2[0][p][nn] = u;
        u.x = pack_bf2(blo1.x, bhi1.x); u.y = pack_bf2(blo1.y, bhi1.y);
        u.z = pack_bf2(blo1.z, bhi1.z); u.w = pack_bf2(blo1.w, bhi1.w);
        *(uint4*)&sm.qk.Bs2[0][p][nn + 4] = u;
    }
    __syncthreads();

    const int NIT = H / 32;
    for (int it = 0; it < NIT; it++) {
        const int buf = it & 1;
        if (it < NIT - 1) {
            const int k0 = (it + 1) * 32;
            a0 = *(const float4*)&xrow[k0];
            a1 = *(const float4*)&xrow[k0 + 4];
            a2 = *(const float4*)&xrow[k0 + 8];
            a3 = *(const float4*)&xrow[k0 + 12];
            blo0 = *(const float4*)&Wm[bbase + (size_t)(k0 + 2 * p)     * D];
            blo1 = *(const float4*)&Wm[bbase + (size_t)(k0 + 2 * p)     * D + 4];
            bhi0 = *(const float4*)&Wm[bbase + (size_t)(k0 + 2 * p + 1) * D];
            bhi1 = *(const float4*)&Wm[bbase + (size_t)(k0 + 2 * p + 1) * D + 4];
        }
#pragma unroll
        for (int ks = 0; ks < 2; ks++) {
            uint32_t af[4][4], bf[4][2];
#pragma unroll
            for (int tm = 0; tm < 4; tm++) {
                const int mb = wm * 64 + tm * 16;
                af[tm][0] = sm.qk.As2[buf][mb + fr][ks * 8 + fc];
                af[tm][1] = sm.qk.As2[buf][mb + fr + 8][ks * 8 + fc];
                af[tm][2] = sm.qk.As2[buf][mb + fr][ks * 8 + fc + 4];
                af[tm][3] = sm.qk.As2[buf][mb + fr + 8][ks * 8 + fc + 4];
            }
#pragma unroll
            for (int tn = 0; tn < 4; tn++) {
                const int nb = wn * 32 + tn * 8 + fr;
                bf[tn][0] = sm.qk.Bs2[buf][ks * 8 + fc][nb];
                bf[tn][1] = sm.qk.Bs2[buf][ks * 8 + fc + 4][nb];
            }
#pragma unroll
            for (int tm = 0; tm < 4; tm++)
#pragma unroll
                for (int tn = 0; tn < 4; tn++)
                    mma_bf16(acc[tm][tn], af[tm], bf[tn]);
        }
        if (it < NIT - 1) {
            const int nb2 = buf ^ 1;
            uint4 u;
            u.x = pack_bf2(a0.x, a0.y); u.y = pack_bf2(a0.z, a0.w);
            u.z = pack_bf2(a1.x, a1.y); u.w = pack_bf2(a1.z, a1.w);
            *(uint4*)&sm.qk.As2[nb2][am][ak / 2] = u;
            u.x = pack_bf2(a2.x, a2.y); u.y = pack_bf2(a2.z, a2.w);
            u.z = pack_bf2(a3.x, a3.y); u.w = pack_bf2(a3.z, a3.w);
            *(uint4*)&sm.qk.As2[nb2][am][ak / 2 + 4] = u;
            u.x = pack_bf2(blo0.x, bhi0.x); u.y = pack_bf2(blo0.y, bhi0.y);
            u.z = pack_bf2(blo0.z, bhi0.z); u.w = pack_bf2(blo0.w, bhi0.w);
            *(uint4*)&sm.qk.Bs2[nb2][p][nn] = u;
            u.x = pack_bf2(blo1.x, bhi1.x); u.y = pack_bf2(blo1.y, bhi1.y);
            u.z = pack_bf2(blo1.z, bhi1.z); u.w = pack_bf2(blo1.w, bhi1.w);
            *(uint4*)&sm.qk.Bs2[nb2][p][nn + 4] = u;
        }
        __syncthreads();
    }

#pragma unroll
    for (int tm = 0; tm < 4; tm++)
#pragma unroll
        for (int tn = 0; tn < 4; tn++) {
            const int row = m0 + wm * 64 + tm * 16 + fr;
            const int col = n0 + wn * 32 + tn * 8 + 2 * fc;
            const float b0 = bias[col], b1 = bias[col + 1];
            __nv_bfloat162 o;
            o = __floats2bfloat162_rn(acc[tm][tn][0] + b0, acc[tm][tn][1] + b1);
            *(__nv_bfloat162*)&C[(size_t)row * H + col] = o;
            o = __floats2bfloat162_rn(acc[tm][tn][2] + b0, acc[tm][tn][3] + b1);
            *(__nv_bfloat162*)&C[(size_t)(row + 8) * H + col] = o;
        }
}

// ---------------------------------------------------------------------------
// Kernel 2: scores via bf16 mma + ldmatrix (EXACT R11). grid = (16,16,NH*B).
// ---------------------------------------------------------------------------
__global__ void __launch_bounds__(256)
scores_bf16()
{
    const int st = blockIdx.x;
    const int tt = blockIdx.y;
    if (st > tt) return;
    const int z = blockIdx.z;
    const int n = z >> 1, b = z & 1;

    const __nv_bfloat16* Qb = g_Qh + (size_t)b * T * H + (size_t)n * D;
    const __nv_bfloat16* Kb = g_Kh + (size_t)b * T * H + (size_t)n * D;
    __half* Wp = g_Wh + (size_t)z * T * T;

    const int t0 = tt * 128, s0 = st * 128;

    __shared__ __align__(16) union {
        struct { uint32_t Q[128][36]; uint32_t K[128][36]; } qk;
        uint32_t S[128][68];
    } sm;
    __shared__ float rs[128][4];

    const int tid  = threadIdx.x;
    const int lane = tid & 31;
    const int wid  = tid >> 5;
    const int wm   = wid >> 2;
    const int wn   = wid & 3;
    const int fr   = lane >> 2;
    const int fc   = lane & 3;

    const int sr = tid >> 1;
    const int sc = (tid & 1) * 32;
#pragma unroll
    for (int u = 0; u < 4; u++) {
        uint4 q4 = *(const uint4*)&Qb[(size_t)(t0 + sr) * H + sc + u * 8];
        uint4 k4 = *(const uint4*)&Kb[(size_t)(s0 + sr) * H + sc + u * 8];
        *(uint4*)&sm.qk.Q[sr][sc / 2 + u * 4] = q4;
        *(uint4*)&sm.qk.K[sr][sc / 2 + u * 4] = k4;
    }
    __syncthreads();

    uint32_t aAddr[4];
    {
        const int lr = lane & 15, lk = (lane >> 4) * 4;
#pragma unroll
        for (int tm = 0; tm < 4; tm++)
            aAddr[tm] = smem_u32(&sm.qk.Q[wm * 64 + tm * 16 + lr][lk]);
    }
    uint32_t bAddr[2];
    {
        const int br = (lane >> 4) * 8 + (lane & 7);
        const int bk = ((lane >> 3) & 1) * 4;
#pragma unroll
        for (int tp = 0; tp < 2; tp++)
            bAddr[tp] = smem_u32(&sm.qk.K[wn * 32 + tp * 16 + br][bk]);
    }

    float acc[4][4][4];
#pragma unroll
    for (int i = 0; i < 4; i++)
#pragma unroll
        for (int j = 0; j < 4; j++)
#pragma unroll
            for (int q = 0; q < 4; q++) acc[i][j][q] = 0.f;

#pragma unroll
    for (int ks = 0; ks < 4; ks++) {
        uint32_t af[4][4], bq0[4], bq1[4];
#pragma unroll
        for (int tm = 0; tm < 4; tm++)
            ldsm_x4(af[tm], aAddr[tm] + ks * 32);
        ldsm_x4(bq0, bAddr[0] + ks * 32);
        ldsm_x4(bq1, bAddr[1] + ks * 32);
        uint32_t bf[4][2];
        bf[0][0] = bq0[0]; bf[0][1] = bq0[1];
        bf[1][0] = bq0[2]; bf[1][1] = bq0[3];
        bf[2][0] = bq1[0]; bf[2][1] = bq1[1];
        bf[3][0] = bq1[2]; bf[3][1] = bq1[3];
#pragma unroll
        for (int tm = 0; tm < 4; tm++)
#pragma unroll
            for (int tn = 0; tn < 4; tn++)
                mma_bf16(acc[tm][tn], af[tm], bf[tn]);
    }

    __syncthreads();

    const bool diag = (st == tt);
#pragma unroll
    for (int tm = 0; tm < 4; tm++)
#pragma unroll
        for (int rq = 0; rq < 2; rq++) {
            const int rloc = wm * 64 + tm * 16 + fr + rq * 8;
            const int t = t0 + rloc;
            float rsum = 0.f;
#pragma unroll
            for (int tn = 0; tn < 4; tn++) {
                const int s = s0 + wn * 32 + tn * 8 + 2 * fc;
                float e0 = __expf(acc[tm][tn][rq * 2 + 0] * SCALE);
                float e1 = __expf(acc[tm][tn][rq * 2 + 1] * SCALE);
                if (diag) {
                    if (s     > t) e0 = 0.f;
                    if (s + 1 > t) e1 = 0.f;
                }
                rsum += e0 + e1;
                __half2 h = __floats2half2_rn(e0, e1);
                sm.S[rloc][wn * 16 + tn * 4 + fc] = *(uint32_t*)&h;
            }
            rsum += __shfl_xor_sync(0xffffffffu, rsum, 1);
            rsum += __shfl_xor_sync(0xffffffffu, rsum, 2);
            if (fc == 0) rs[rloc][wn] = rsum;
        }
    __syncthreads();

    if (tid < 128) {
        float v = rs[tid][0] + rs[tid][1] + rs[tid][2] + rs[tid][3];
        g_RS[((size_t)z * T + t0 + tid) * 16 + st] = v;
    }

    const int rr0 = tid >> 4;
    const int cw  = (tid & 15) * 4;
#pragma unroll
    for (int i = 0; i < 8; i++) {
        const int rr = rr0 + i * 16;
        uint4 v = *(const uint4*)&sm.S[rr][cw];
        *(uint4*)&Wp[(size_t)(t0 + rr) * T + s0 + cw * 2] = v;
    }
}

// ---------------------------------------------------------------------------
// Kernel 3: streaming mean-of-softmax; writes fp32 output + fp16 copy.
// ---------------------------------------------------------------------------
__global__ void __launch_bounds__(256)
softmax_mean_kernel(float* __restrict__ out_mean)
{
    const int row = (B * T - 1) - blockIdx.x;
    const int b = row >> 11;
    const int t = row & 2047;
    const int tid = threadIdx.x;

    const int nst = (t >> 7) + 1;
    const int L   = nst * 128;

    __shared__ float sinv[NH];
    if (tid < NH) {
        const float* p = g_RS + ((size_t)(tid * B + b) * T + t) * 16;
        float s = 0.f;
        for (int i = 0; i < nst; i++) s += p[i];
        sinv[tid] = (1.0f / NH) / s;
    }
    __syncthreads();

    const int c0 = tid * 8;
    float acc[8];
#pragma unroll
    for (int i = 0; i < 8; i++) acc[i] = 0.f;

    if (c0 < L) {
        const size_t rowoff = ((size_t)b * T + t) * T + c0;
#pragma unroll
        for (int n = 0; n < NH; n++) {
            const __half* p = g_Wh + (size_t)n * (B * (size_t)T * T) + rowoff;
            uint4 u = *(const uint4*)p;
            const float w = sinv[n];
            float2 f;
            f = __half22float2(*(__half2*)&u.x); acc[0] += f.x * w; acc[1] += f.y * w;
            f = __half22float2(*((__half2*)&u.x + 1)); acc[2] += f.x * w; acc[3] += f.y * w;
            f = __half22float2(*(__half2*)&u.z); acc[4] += f.x * w; acc[5] += f.y * w;
            f = __half22float2(*((__half2*)&u.z + 1)); acc[6] += f.x * w; acc[7] += f.y * w;
        }
    }

    float* mrow = out_mean + (size_t)row * T + c0;
    *(float4*)&mrow[0] = make_float4(acc[0], acc[1], acc[2], acc[3]);
    *(float4*)&mrow[4] = make_float4(acc[4], acc[5], acc[6], acc[7]);

    uint4 hq;
    __half2 h;
    h = __floats2half2_rn(acc[0], acc[1]); hq.x = *(uint32_t*)&h;
    h = __floats2half2_rn(acc[2], acc[3]); hq.y = *(uint32_t*)&h;
    h = __floats2half2_rn(acc[4], acc[5]); hq.z = *(uint32_t*)&h;
    h = __floats2half2_rn(acc[6], acc[7]); hq.w = *(uint32_t*)&h;
    *(uint4*)&g_MWh[(size_t)row * T + c0] = hq;
}

// ---------------------------------------------------------------------------
// Kernel 4: AV via fp16 mma + ldmatrix. CTA tile 128 t x 64 d, 8 s-chunks.
// grid = (16, B, 8), 256 threads.
// ---------------------------------------------------------------------------
__global__ void __launch_bounds__(256)
av_fp16()
{
    const int tt    = blockIdx.x;
    const int b     = blockIdx.y;
    const int chunk = blockIdx.z;
    const int t0 = tt * 128;

    const int st_begin = chunk * 4;
    const int st_end   = min(chunk * 4 + 4, ((t0 + 127) >> 6) + 1);

    __shared__ __align__(16) uint32_t Aw[128][36];
    __shared__ __align__(16) uint32_t Bw[64][36];

    const int tid  = threadIdx.x;
    const int lane = tid & 31;
    const int wid  = tid >> 5;
    const int wm   = wid >> 1;
    const int wn   = wid & 1;
    const int fr   = lane >> 2;
    const int fc   = lane & 3;

    const int asr = tid >> 1;
    const int asc = (tid & 1) * 32;
    const int bsr = tid >> 2;
    const int bsc = (tid & 3) * 16;

    uint32_t aAddr[2];
    {
        const int lr = lane & 15, lk = (lane >> 4) * 4;
#pragma unroll
        for (int tm = 0; tm < 2; tm++)
            aAddr[tm] = smem_u32(&Aw[wm * 32 + tm * 16 + lr][lk]);
    }
    uint32_t bAddr[2];
    {
        const int br = (lane >> 4) * 8 + (lane & 7);
        const int bk = ((lane >> 3) & 1) * 4;
#pragma unroll
        for (int tp = 0; tp < 2; tp++)
            bAddr[tp] = smem_u32(&Bw[wn * 32 + tp * 16 + br][bk]);
    }

    float acc[2][4][4];
#pragma unroll
    for (int i = 0; i < 2; i++)
#pragma unroll
        for (int j = 0; j < 4; j++)
#pragma unroll
            for (int q = 0; q < 4; q++) acc[i][j][q] = 0.f;

    for (int st = st_begin; st < st_end; st++) {
        const int s0 = st * 64;
        if (st > st_begin) __syncthreads();
        {
            const __half* src = g_MWh + ((size_t)b * T + t0 + asr) * T + s0 + asc;
#pragma unroll
            for (int u = 0; u < 4; u++)
                *(uint4*)&Aw[asr][asc / 2 + u * 4] = *(const uint4*)&src[u * 8];
        }
        {
            const __half* src = g_Vth + ((size_t)b * D + bsr) * T + s0 + bsc;
#pragma unroll
            for (int u = 0; u < 2; u++)
                *(uint4*)&Bw[bsr][bsc / 2 + u * 4] = *(const uint4*)&src[u * 8];
        }
        __syncthreads();

#pragma unroll
        for (int ks = 0; ks < 4; ks++) {
            uint32_t af[2][4], bq0[4], bq1[4];
#pragma unroll
            for (int tm = 0; tm < 2; tm++)
                ldsm_x4(af[tm], aAddr[tm] + ks * 32);
            ldsm_x4(bq0, bAddr[0] + ks * 32);
            ldsm_x4(bq1, bAddr[1] + ks * 32);
            uint32_t bf[4][2];
            bf[0][0] = bq0[0]; bf[0][1] = bq0[1];
            bf[1][0] = bq0[2]; bf[1][1] = bq0[3];
            bf[2][0] = bq1[0]; bf[2][1] = bq1[1];
            bf[3][0] = bq1[2]; bf[3][1] = bq1[3];
#pragma unroll
            for (int tm = 0; tm < 2; tm++)
#pragma unroll
                for (int tn = 0; tn < 4; tn++)
                    mma_fp16(acc[tm][tn], af[tm], bf[tn]);
        }
    }

    float* Cp = g_MHp + (size_t)chunk * B * T * D;
#pragma unroll
    for (int tm = 0; tm < 2; tm++)
#pragma unroll
        for (int tn = 0; tn < 4; tn++) {
            const int t = t0 + wm * 32 + tm * 16 + fr;
            const int d = wn * 32 + tn * 8 + 2 * fc;
            float2 o;
            o.x = acc[tm][tn][0]; o.y = acc[tm][tn][1];
            *(float2*)&Cp[((size_t)b * T + t) * D + d] = o;
            o.x = acc[tm][tn][2]; o.y = acc[tm][tn][3];
            *(float2*)&Cp[((size_t)b * T + t + 8) * D + d] = o;
        }
}

// mhsum: g_MH = sum of 8 AV partials (fixed order). grid = B*T*D/256.
__global__ void mhsum_kernel()
{
    const size_t i = (size_t)blockIdx.x * 256 + threadIdx.x;
    const size_t N = (size_t)B * T * D;
    float v = 0.f;
#pragma unroll
    for (int p = 0; p < 8; p++) v += g_MHp[p * N + i];
    g_MH[i] = v;
}

// ---------------------------------------------------------------------------
// Kernel 5: out = g_MH @ Wo + bo. grid = (H/64, B*T/64).
// ---------------------------------------------------------------------------
__global__ void out_kernel(const float* __restrict__ Wo,
                           const float* __restrict__ bo,
                           float* __restrict__ out)
{
    const int n0 = blockIdx.x * 64;
    const int m0 = blockIdx.y * 64;

    __shared__ float As[64][65];
    __shared__ float Bs[64][65];

    const int tx = threadIdx.x, ty = threadIdx.y;
    const int tid = ty * 16 + tx;

#pragma unroll
    for (int i = 0; i < 16; i++) {
        int idx = tid + i * 256;
        int r = idx >> 6, c = idx & 63;
        As[r][c] = g_MH[(size_t)(m0 + r) * D + c];
        Bs[r][c] = Wo[(size_t)r * H + n0 + c];
    }
    __syncthreads();

    float acc[4][4];
#pragma unroll
    for (int i = 0; i < 4; i++)
#pragma unroll
        for (int j = 0; j < 4; j++) acc[i][j] = 0.f;

#pragma unroll 8
    for (int kk = 0; kk < 64; kk++) {
        float a[4], bb[4];
#pragma unroll
        for (int i = 0; i < 4; i++) a[i]  = As[ty * 4 + i][kk];
#pragma unroll
        for (int j = 0; j < 4; j++) bb[j] = Bs[kk][tx * 4 + j];
#pragma unroll
        for (int i = 0; i < 4; i++)
#pragma unroll
            for (int j = 0; j < 4; j++) acc[i][j] += a[i] * bb[j];
    }

#pragma unroll
    for (int i = 0; i < 4; i++)
#pragma unroll
        for (int j = 0; j < 4; j++)
            out[(size_t)(m0 + ty * 4 + i) * H + n0 + tx * 4 + j] =
                acc[i][j] + bo[n0 + tx * 4 + j];
}

// ---------------------------------------------------------------------------
extern "C" void kernel_launch(void* const* d_in, const int* in_sizes, int n_in,
                              void* d_out, int out_size)
{
    const float* x  = (const float*)d_in[0];
    const float* Wq = (const float*)d_in[1];
    const float* bq = (const float*)d_in[2];
    const float* Wk = (const float*)d_in[3];
    const float* bk = (const float*)d_in[4];
    const float* Wv = (const float*)d_in[5];
    const float* bv = (const float*)d_in[6];
    const float* Wo = (const float*)d_in[7];
    const float* bo = (const float*)d_in[8];

    float* out      = (float*)d_out;                 // [B,T,H]
    float* mean_out = out + (size_t)B * T * H;       // [B,T,T]

    dim3 blk16(16, 16);

    qkvproj_kernel     <<<dim3(8, 32, 3), 256>>>(x, Wq, bq, Wk, bk, Wv, bv);
    scores_bf16        <<<dim3(T / 128, T / 128, NH * B), 256>>>();
    softmax_mean_kernel<<<B * T, 256>>>(mean_out);
    av_fp16            <<<dim3(T / 128, B, 8), 256>>>();
    mhsum_kernel       <<<(B * T * D) / 256, 256>>>();
    out_kernel         <<<dim3(H / 64, (B * T) / 64), blk16>>>(Wo, bo, out);
}

// round 13
// speedup vs baseline: 1.0959x; 1.0959x over previous
#include <cuda_runtime.h>
#include <cuda_fp16.h>
#include <cuda_bf16.h>
#include <math.h>
#include <stdint.h>

#define B    2
#define T    2048
#define H    1024
#define NH   16
#define D    64
#define SCALE 0.125f   // D^-0.5

// ---------------- static device scratch (no dynamic allocation allowed) ----
__device__ __nv_bfloat16 g_Qh[(size_t)B * T * H];   // 8 MB
__device__ __nv_bfloat16 g_Kh[(size_t)B * T * H];   // 8 MB
__device__ float  g_Vp[(size_t)4 * B * T * D];      // 4 MB V split-K partials
__device__ __half g_Vth[(size_t)B * D * T];         // 0.5 MB V transposed fp16 [b][d][t]
__device__ __half g_Wh[(size_t)NH * B * T * T];     // 268 MB exp(score) fp16
__device__ __half g_MWh[(size_t)B * T * T];         // 16 MB mean_weights fp16 copy
__device__ float  g_RS[(size_t)NH * B * T * 16];    // 4 MB per-(row,s-tile) exp sums
__device__ float  g_MHp[(size_t)8 * B * T * D];     // 8 MB AV partials (8 chunks)
__device__ float  g_MH[(size_t)B * T * D];          // 1 MB reduced mean_head

// ---------------------------------------------------------------------------
__device__ __forceinline__ uint32_t pack_bf2(float lo, float hi) {
    __nv_bfloat162 h = __floats2bfloat162_rn(lo, hi);
    return *(uint32_t*)&h;
}

__device__ __forceinline__ void mma_bf16(float* d, const uint32_t* a, const uint32_t* b) {
    asm volatile(
        "mma.sync.aligned.m16n8k16.row.col.f32.bf16.bf16.f32 "
        "{%0,%1,%2,%3}, {%4,%5,%6,%7}, {%8,%9}, {%0,%1,%2,%3};"
        : "+f"(d[0]), "+f"(d[1]), "+f"(d[2]), "+f"(d[3])
        : "r"(a[0]), "r"(a[1]), "r"(a[2]), "r"(a[3]), "r"(b[0]), "r"(b[1]));
}

__device__ __forceinline__ void mma_fp16(float* d, const uint32_t* a, const uint32_t* b) {
    asm volatile(
        "mma.sync.aligned.m16n8k16.row.col.f32.f16.f16.f32 "
        "{%0,%1,%2,%3}, {%4,%5,%6,%7}, {%8,%9}, {%0,%1,%2,%3};"
        : "+f"(d[0]), "+f"(d[1]), "+f"(d[2]), "+f"(d[3])
        : "r"(a[0]), "r"(a[1]), "r"(a[2]), "r"(a[3]), "r"(b[0]), "r"(b[1]));
}

__device__ __forceinline__ uint32_t smem_u32(const void* p) {
    uint32_t a;
    asm("{ .reg .u64 t; cvta.to.shared.u64 t, %1; cvt.u32.u64 %0, t; }"
        : "=r"(a) : "l"(p));
    return a;
}

__device__ __forceinline__ void ldsm_x4(uint32_t* r, uint32_t addr) {
    asm volatile("ldmatrix.sync.aligned.m8n8.x4.shared.b16 {%0,%1,%2,%3}, [%4];"
        : "=r"(r[0]), "=r"(r[1]), "=r"(r[2]), "=r"(r[3]) : "r"(addr));
}

// ---------------------------------------------------------------------------
// Kernel 1: batched Q/K projection, bf16 mma (EXACT R11 standalone version).
// grid = (8, 32, 2)  z: 0->Q, 1->K
// ---------------------------------------------------------------------------
__global__ void __launch_bounds__(256)
qkproj_bf16(const float* __restrict__ x,
            const float* __restrict__ Wq, const float* __restrict__ bq,
            const float* __restrict__ Wk, const float* __restrict__ bk)
{
    const float* Wm    = blockIdx.z ? Wk : Wq;
    const float* bias  = blockIdx.z ? bk : bq;
    __nv_bfloat16* C   = blockIdx.z ? g_Kh : g_Qh;
    const int n0 = blockIdx.x * 128;
    const int m0 = blockIdx.y * 128;

    __shared__ __align__(16) uint32_t As2[2][128][20];
    __shared__ __align__(16) uint32_t Bs2[2][16][136];

    const int tid  = threadIdx.x;
    const int lane = tid & 31;
    const int wid  = tid >> 5;
    const int wm   = wid >> 2;
    const int wn   = wid & 3;
    const int fr   = lane >> 2;
    const int fc   = lane & 3;

    const int am = tid >> 1;
    const int ak = (tid & 1) * 16;
    const float* xrow = x + (size_t)(m0 + am) * H + ak;
    const int p  = tid >> 4;
    const int nn = (tid & 15) * 8;
    const int bcol = n0 + nn;
    const size_t bbase = (size_t)(bcol >> 6) * (H * D) + (size_t)(bcol & 63);

    float acc[4][4][4];
#pragma unroll
    for (int i = 0; i < 4; i++)
#pragma unroll
        for (int j = 0; j < 4; j++)
#pragma unroll
            for (int q = 0; q < 4; q++) acc[i][j][q] = 0.f;

    float4 a0, a1, a2, a3, blo0, blo1, bhi0, bhi1;

    a0 = *(const float4*)&xrow[0];
    a1 = *(const float4*)&xrow[4];
    a2 = *(const float4*)&xrow[8];
    a3 = *(const float4*)&xrow[12];
    blo0 = *(const float4*)&Wm[bbase + (size_t)(2 * p)     * D];
    blo1 = *(const float4*)&Wm[bbase + (size_t)(2 * p)     * D + 4];
    bhi0 = *(const float4*)&Wm[bbase + (size_t)(2 * p + 1) * D];
    bhi1 = *(const float4*)&Wm[bbase + (size_t)(2 * p + 1) * D + 4];
    {
        uint4 u;
        u.x = pack_bf2(a0.x, a0.y); u.y = pack_bf2(a0.z, a0.w);
        u.z = pack_bf2(a1.x, a1.y); u.w = pack_bf2(a1.z, a1.w);
        *(uint4*)&As2[0][am][ak / 2] = u;
        u.x = pack_bf2(a2.x, a2.y); u.y = pack_bf2(a2.z, a2.w);
        u.z = pack_bf2(a3.x, a3.y); u.w = pack_bf2(a3.z, a3.w);
        *(uint4*)&As2[0][am][ak / 2 + 4] = u;
        u.x = pack_bf2(blo0.x, bhi0.x); u.y = pack_bf2(blo0.y, bhi0.y);
        u.z = pack_bf2(blo0.z, bhi0.z); u.w = pack_bf2(blo0.w, bhi0.w);
        *(uint4*)&Bs2[0][p][nn] = u;
        u.x = pack_bf2(blo1.x, bhi1.x); u.y = pack_bf2(blo1.y, bhi1.y);
        u.z = pack_bf2(blo1.z, bhi1.z); u.w = pack_bf2(blo1.w, bhi1.w);
        *(uint4*)&Bs2[0][p][nn + 4] = u;
    }
    __syncthreads();

    const int NIT = H / 32;
    for (int it = 0; it < NIT; it++) {
        const int buf = it & 1;
        if (it < NIT - 1) {
            const int k0 = (it + 1) * 32;
            a0 = *(const float4*)&xrow[k0];
            a1 = *(const float4*)&xrow[k0 + 4];
            a2 = *(const float4*)&xrow[k0 + 8];
            a3 = *(const float4*)&xrow[k0 + 12];
            blo0 = *(const float4*)&Wm[bbase + (size_t)(k0 + 2 * p)     * D];
            blo1 = *(const float4*)&Wm[bbase + (size_t)(k0 + 2 * p)     * D + 4];
            bhi0 = *(const float4*)&Wm[bbase + (size_t)(k0 + 2 * p + 1) * D];
            bhi1 = *(const float4*)&Wm[bbase + (size_t)(k0 + 2 * p + 1) * D + 4];
        }
#pragma unroll
        for (int ks = 0; ks < 2; ks++) {
            uint32_t af[4][4], bf[4][2];
#pragma unroll
            for (int tm = 0; tm < 4; tm++) {
                const int mb = wm * 64 + tm * 16;
                af[tm][0] = As2[buf][mb + fr][ks * 8 + fc];
                af[tm][1] = As2[buf][mb + fr + 8][ks * 8 + fc];
                af[tm][2] = As2[buf][mb + fr][ks * 8 + fc + 4];
                af[tm][3] = As2[buf][mb + fr + 8][ks * 8 + fc + 4];
            }
#pragma unroll
            for (int tn = 0; tn < 4; tn++) {
                const int nb = wn * 32 + tn * 8 + fr;
                bf[tn][0] = Bs2[buf][ks * 8 + fc][nb];
                bf[tn][1] = Bs2[buf][ks * 8 + fc + 4][nb];
            }
#pragma unroll
            for (int tm = 0; tm < 4; tm++)
#pragma unroll
                for (int tn = 0; tn < 4; tn++)
                    mma_bf16(acc[tm][tn], af[tm], bf[tn]);
        }
        if (it < NIT - 1) {
            const int nb2 = (it & 1) ^ 1;
            uint4 u;
            u.x = pack_bf2(a0.x, a0.y); u.y = pack_bf2(a0.z, a0.w);
            u.z = pack_bf2(a1.x, a1.y); u.w = pack_bf2(a1.z, a1.w);
            *(uint4*)&As2[nb2][am][ak / 2] = u;
            u.x = pack_bf2(a2.x, a2.y); u.y = pack_bf2(a2.z, a2.w);
            u.z = pack_bf2(a3.x, a3.y); u.w = pack_bf2(a3.z, a3.w);
            *(uint4*)&As2[nb2][am][ak / 2 + 4] = u;
            u.x = pack_bf2(blo0.x, bhi0.x); u.y = pack_bf2(blo0.y, bhi0.y);
            u.z = pack_bf2(blo0.z, bhi0.z); u.w = pack_bf2(blo0.w, bhi0.w);
            *(uint4*)&Bs2[nb2][p][nn] = u;
            u.x = pack_bf2(blo1.x, bhi1.x); u.y = pack_bf2(blo1.y, bhi1.y);
            u.z = pack_bf2(blo1.z, bhi1.z); u.w = pack_bf2(blo1.w, bhi1.w);
            *(uint4*)&Bs2[nb2][p][nn + 4] = u;
        }
        __syncthreads();
    }

#pragma unroll
    for (int tm = 0; tm < 4; tm++)
#pragma unroll
        for (int tn = 0; tn < 4; tn++) {
            const int row = m0 + wm * 64 + tm * 16 + fr;
            const int col = n0 + wn * 32 + tn * 8 + 2 * fc;
            const float b0 = bias[col], b1 = bias[col + 1];
            __nv_bfloat162 o;
            o = __floats2bfloat162_rn(acc[tm][tn][0] + b0, acc[tm][tn][1] + b1);
            *(__nv_bfloat162*)&C[(size_t)row * H + col] = o;
            o = __floats2bfloat162_rn(acc[tm][tn][2] + b0, acc[tm][tn][3] + b1);
            *(__nv_bfloat162*)&C[(size_t)(row + 8) * H + col] = o;
        }
}

// ---------------------------------------------------------------------------
// Kernel 2: V projection, split-K fp32 (EXACT R11). grid = (B*T/64, 4).
// ---------------------------------------------------------------------------
__global__ void vproj_kernel(const float* __restrict__ x,
                             const float* __restrict__ Wv)
{
    const int m0 = blockIdx.x * 64;
    const int kbase = blockIdx.y * (H / 4);
    float* Cp = g_Vp + (size_t)blockIdx.y * B * T * D;

    __shared__ float As[64][17];
    __shared__ float Bs[16][65];

    const int tx = threadIdx.x, ty = threadIdx.y;
    const int tid = ty * 16 + tx;

    float acc[4][4];
#pragma unroll
    for (int i = 0; i < 4; i++)
#pragma unroll
        for (int j = 0; j < 4; j++) acc[i][j] = 0.f;

    for (int kc = 0; kc < H / 4; kc += 16) {
        const int k0 = kbase + kc;
#pragma unroll
        for (int i = 0; i < 4; i++) {
            int idx = tid + i * 256;
            int r = idx >> 4, c = idx & 15;
            As[r][c] = x[(size_t)(m0 + r) * H + k0 + c];
        }
#pragma unroll
        for (int i = 0; i < 4; i++) {
            int idx = tid + i * 256;
            int r = idx >> 6, c = idx & 63;
            Bs[r][c] = Wv[(size_t)(k0 + r) * D + c];
        }
        __syncthreads();
#pragma unroll
        for (int kk = 0; kk < 16; kk++) {
            float a[4], bb[4];
#pragma unroll
            for (int i = 0; i < 4; i++) a[i]  = As[ty * 4 + i][kk];
#pragma unroll
            for (int j = 0; j < 4; j++) bb[j] = Bs[kk][tx * 4 + j];
#pragma unroll
            for (int i = 0; i < 4; i++)
#pragma unroll
                for (int j = 0; j < 4; j++) acc[i][j] += a[i] * bb[j];
        }
        __syncthreads();
    }
#pragma unroll
    for (int i = 0; i < 4; i++)
#pragma unroll
        for (int j = 0; j < 4; j++)
            Cp[(size_t)(m0 + ty * 4 + i) * D + tx * 4 + j] = acc[i][j];
}

// vtsum: sum 4 partials + bias, write transposed fp16 g_Vth[b][d][t].
// grid = B*T/64, 256 threads. smem transpose, conflict-free both phases.
__global__ void vtsum_kernel(const float* __restrict__ bv)
{
    __shared__ float tile[64][65];
    const int m0 = blockIdx.x * 64;        // t rows
    const int b  = m0 >> 11;
    const int t0 = m0 & 2047;
    const int tid = threadIdx.x;
    const size_t N = (size_t)B * T * D;

#pragma unroll
    for (int i = 0; i < 16; i++) {
        const int idx = tid + i * 256;     // 0..4095
        const int r = idx >> 6, c = idx & 63;
        const size_t mi = (size_t)(m0 + r) * D + c;
        tile[r][c] = g_Vp[mi] + g_Vp[N + mi] + g_Vp[2 * N + mi]
                   + g_Vp[3 * N + mi] + bv[c];
    }
    __syncthreads();
#pragma unroll
    for (int i = 0; i < 16; i++) {
        const int idx = tid + i * 256;
        const int d = idx >> 6, tc = idx & 63;   // output row d, col t
        g_Vth[((size_t)b * D + d) * T + t0 + tc] = __float2half(tile[tc][d]);
    }
}

// ---------------------------------------------------------------------------
// Kernel 3: scores via bf16 mma + ldmatrix (EXACT R11). grid = (16,16,NH*B).
// ---------------------------------------------------------------------------
__global__ void __launch_bounds__(256)
scores_bf16()
{
    const int st = blockIdx.x;
    const int tt = blockIdx.y;
    if (st > tt) return;
    const int z = blockIdx.z;
    const int n = z >> 1, b = z & 1;

    const __nv_bfloat16* Qb = g_Qh + (size_t)b * T * H + (size_t)n * D;
    const __nv_bfloat16* Kb = g_Kh + (size_t)b * T * H + (size_t)n * D;
    __half* Wp = g_Wh + (size_t)z * T * T;

    const int t0 = tt * 128, s0 = st * 128;

    __shared__ __align__(16) union {
        struct { uint32_t Q[128][36]; uint32_t K[128][36]; } qk;
        uint32_t S[128][68];
    } sm;
    __shared__ float rs[128][4];

    const int tid  = threadIdx.x;
    const int lane = tid & 31;
    const int wid  = tid >> 5;
    const int wm   = wid >> 2;
    const int wn   = wid & 3;
    const int fr   = lane >> 2;
    const int fc   = lane & 3;

    const int sr = tid >> 1;
    const int sc = (tid & 1) * 32;
#pragma unroll
    for (int u = 0; u < 4; u++) {
        uint4 q4 = *(const uint4*)&Qb[(size_t)(t0 + sr) * H + sc + u * 8];
        uint4 k4 = *(const uint4*)&Kb[(size_t)(s0 + sr) * H + sc + u * 8];
        *(uint4*)&sm.qk.Q[sr][sc / 2 + u * 4] = q4;
        *(uint4*)&sm.qk.K[sr][sc / 2 + u * 4] = k4;
    }
    __syncthreads();

    uint32_t aAddr[4];
    {
        const int lr = lane & 15, lk = (lane >> 4) * 4;
#pragma unroll
        for (int tm = 0; tm < 4; tm++)
            aAddr[tm] = smem_u32(&sm.qk.Q[wm * 64 + tm * 16 + lr][lk]);
    }
    uint32_t bAddr[2];
    {
        const int br = (lane >> 4) * 8 + (lane & 7);
        const int bk = ((lane >> 3) & 1) * 4;
#pragma unroll
        for (int tp = 0; tp < 2; tp++)
            bAddr[tp] = smem_u32(&sm.qk.K[wn * 32 + tp * 16 + br][bk]);
    }

    float acc[4][4][4];
#pragma unroll
    for (int i = 0; i < 4; i++)
#pragma unroll
        for (int j = 0; j < 4; j++)
#pragma unroll
            for (int q = 0; q < 4; q++) acc[i][j][q] = 0.f;

#pragma unroll
    for (int ks = 0; ks < 4; ks++) {
        uint32_t af[4][4], bq0[4], bq1[4];
#pragma unroll
        for (int tm = 0; tm < 4; tm++)
            ldsm_x4(af[tm], aAddr[tm] + ks * 32);
        ldsm_x4(bq0, bAddr[0] + ks * 32);
        ldsm_x4(bq1, bAddr[1] + ks * 32);
        uint32_t bf[4][2];
        bf[0][0] = bq0[0]; bf[0][1] = bq0[1];
        bf[1][0] = bq0[2]; bf[1][1] = bq0[3];
        bf[2][0] = bq1[0]; bf[2][1] = bq1[1];
        bf[3][0] = bq1[2]; bf[3][1] = bq1[3];
#pragma unroll
        for (int tm = 0; tm < 4; tm++)
#pragma unroll
            for (int tn = 0; tn < 4; tn++)
                mma_bf16(acc[tm][tn], af[tm], bf[tn]);
    }

    __syncthreads();

    const bool diag = (st == tt);
#pragma unroll
    for (int tm = 0; tm < 4; tm++)
#pragma unroll
        for (int rq = 0; rq < 2; rq++) {
            const int rloc = wm * 64 + tm * 16 + fr + rq * 8;
            const int t = t0 + rloc;
            float rsum = 0.f;
#pragma unroll
            for (int tn = 0; tn < 4; tn++) {
                const int s = s0 + wn * 32 + tn * 8 + 2 * fc;
                float e0 = __expf(acc[tm][tn][rq * 2 + 0] * SCALE);
                float e1 = __expf(acc[tm][tn][rq * 2 + 1] * SCALE);
                if (diag) {
                    if (s     > t) e0 = 0.f;
                    if (s + 1 > t) e1 = 0.f;
                }
                rsum += e0 + e1;
                __half2 h = __floats2half2_rn(e0, e1);
                sm.S[rloc][wn * 16 + tn * 4 + fc] = *(uint32_t*)&h;
            }
            rsum += __shfl_xor_sync(0xffffffffu, rsum, 1);
            rsum += __shfl_xor_sync(0xffffffffu, rsum, 2);
            if (fc == 0) rs[rloc][wn] = rsum;
        }
    __syncthreads();

    if (tid < 128) {
        float v = rs[tid][0] + rs[tid][1] + rs[tid][2] + rs[tid][3];
        g_RS[((size_t)z * T + t0 + tid) * 16 + st] = v;
    }

    const int rr0 = tid >> 4;
    const int cw  = (tid & 15) * 4;
#pragma unroll
    for (int i = 0; i < 8; i++) {
        const int rr = rr0 + i * 16;
        uint4 v = *(const uint4*)&sm.S[rr][cw];
        *(uint4*)&Wp[(size_t)(t0 + rr) * T + s0 + cw * 2] = v;
    }
}

// ---------------------------------------------------------------------------
// Kernel 4: streaming mean-of-softmax; fp32 output + fp16 copy for AV.
// ---------------------------------------------------------------------------
__global__ void __launch_bounds__(256)
softmax_mean_kernel(float* __restrict__ out_mean)
{
    const int row = (B * T - 1) - blockIdx.x;
    const int b = row >> 11;
    const int t = row & 2047;
    const int tid = threadIdx.x;

    const int nst = (t >> 7) + 1;
    const int L   = nst * 128;

    __shared__ float sinv[NH];
    if (tid < NH) {
        const float* p = g_RS + ((size_t)(tid * B + b) * T + t) * 16;
        float s = 0.f;
        for (int i = 0; i < nst; i++) s += p[i];
        sinv[tid] = (1.0f / NH) / s;
    }
    __syncthreads();

    const int c0 = tid * 8;
    float acc[8];
#pragma unroll
    for (int i = 0; i < 8; i++) acc[i] = 0.f;

    if (c0 < L) {
        const size_t rowoff = ((size_t)b * T + t) * T + c0;
#pragma unroll
        for (int n = 0; n < NH; n++) {
            const __half* p = g_Wh + (size_t)n * (B * (size_t)T * T) + rowoff;
            uint4 u = *(const uint4*)p;
            const float w = sinv[n];
            float2 f;
            f = __half22float2(*(__half2*)&u.x); acc[0] += f.x * w; acc[1] += f.y * w;
            f = __half22float2(*((__half2*)&u.x + 1)); acc[2] += f.x * w; acc[3] += f.y * w;
            f = __half22float2(*(__half2*)&u.z); acc[4] += f.x * w; acc[5] += f.y * w;
            f = __half22float2(*((__half2*)&u.z + 1)); acc[6] += f.x * w; acc[7] += f.y * w;
        }
    }

    float* mrow = out_mean + (size_t)row * T + c0;
    *(float4*)&mrow[0] = make_float4(acc[0], acc[1], acc[2], acc[3]);
    *(float4*)&mrow[4] = make_float4(acc[4], acc[5], acc[6], acc[7]);

    uint4 hq;
    __half2 h;
    h = __floats2half2_rn(acc[0], acc[1]); hq.x = *(uint32_t*)&h;
    h = __floats2half2_rn(acc[2], acc[3]); hq.y = *(uint32_t*)&h;
    h = __floats2half2_rn(acc[4], acc[5]); hq.z = *(uint32_t*)&h;
    h = __floats2half2_rn(acc[6], acc[7]); hq.w = *(uint32_t*)&h;
    *(uint4*)&g_MWh[(size_t)row * T + c0] = hq;
}

// ---------------------------------------------------------------------------
// Kernel 5: AV via fp16 mma + ldmatrix (EXACT R12). grid = (16, B, 8).
// ---------------------------------------------------------------------------
__global__ void __launch_bounds__(256)
av_fp16()
{
    const int tt    = blockIdx.x;
    const int b     = blockIdx.y;
    const int chunk = blockIdx.z;
    const int t0 = tt * 128;

    const int st_begin = chunk * 4;
    const int st_end   = min(chunk * 4 + 4, ((t0 + 127) >> 6) + 1);

    __shared__ __align__(16) uint32_t Aw[128][36];
    __shared__ __align__(16) uint32_t Bw[64][36];

    const int tid  = threadIdx.x;
    const int lane = tid & 31;
    const int wid  = tid >> 5;
    const int wm   = wid >> 1;
    const int wn   = wid & 1;
    const int fr   = lane >> 2;
    const int fc   = lane & 3;

    const int asr = tid >> 1;
    const int asc = (tid & 1) * 32;
    const int bsr = tid >> 2;
    const int bsc = (tid & 3) * 16;

    uint32_t aAddr[2];
    {
        const int lr = lane & 15, lk = (lane >> 4) * 4;
#pragma unroll
        for (int tm = 0; tm < 2; tm++)
            aAddr[tm] = smem_u32(&Aw[wm * 32 + tm * 16 + lr][lk]);
    }
    uint32_t bAddr[2];
    {
        const int br = (lane >> 4) * 8 + (lane & 7);
        const int bk = ((lane >> 3) & 1) * 4;
#pragma unroll
        for (int tp = 0; tp < 2; tp++)
            bAddr[tp] = smem_u32(&Bw[wn * 32 + tp * 16 + br][bk]);
    }

    float acc[2][4][4];
#pragma unroll
    for (int i = 0; i < 2; i++)
#pragma unroll
        for (int j = 0; j < 4; j++)
#pragma unroll
            for (int q = 0; q < 4; q++) acc[i][j][q] = 0.f;

    for (int st = st_begin; st < st_end; st++) {
        const int s0 = st * 64;
        if (st > st_begin) __syncthreads();
        {
            const __half* src = g_MWh + ((size_t)b * T + t0 + asr) * T + s0 + asc;
#pragma unroll
            for (int u = 0; u < 4; u++)
                *(uint4*)&Aw[asr][asc / 2 + u * 4] = *(const uint4*)&src[u * 8];
        }
        {
            const __half* src = g_Vth + ((size_t)b * D + bsr) * T + s0 + bsc;
#pragma unroll
            for (int u = 0; u < 2; u++)
                *(uint4*)&Bw[bsr][bsc / 2 + u * 4] = *(const uint4*)&src[u * 8];
        }
        __syncthreads();

#pragma unroll
        for (int ks = 0; ks < 4; ks++) {
            uint32_t af[2][4], bq0[4], bq1[4];
#pragma unroll
            for (int tm = 0; tm < 2; tm++)
                ldsm_x4(af[tm], aAddr[tm] + ks * 32);
            ldsm_x4(bq0, bAddr[0] + ks * 32);
            ldsm_x4(bq1, bAddr[1] + ks * 32);
            uint32_t bf[4][2];
            bf[0][0] = bq0[0]; bf[0][1] = bq0[1];
            bf[1][0] = bq0[2]; bf[1][1] = bq0[3];
            bf[2][0] = bq1[0]; bf[2][1] = bq1[1];
            bf[3][0] = bq1[2]; bf[3][1] = bq1[3];
#pragma unroll
            for (int tm = 0; tm < 2; tm++)
#pragma unroll
                for (int tn = 0; tn < 4; tn++)
                    mma_fp16(acc[tm][tn], af[tm], bf[tn]);
        }
    }

    float* Cp = g_MHp + (size_t)chunk * B * T * D;
#pragma unroll
    for (int tm = 0; tm < 2; tm++)
#pragma unroll
        for (int tn = 0; tn < 4; tn++) {
            const int t = t0 + wm * 32 + tm * 16 + fr;
            const int d = wn * 32 + tn * 8 + 2 * fc;
            float2 o;
            o.x = acc[tm][tn][0]; o.y = acc[tm][tn][1];
            *(float2*)&Cp[((size_t)b * T + t) * D + d] = o;
            o.x = acc[tm][tn][2]; o.y = acc[tm][tn][3];
            *(float2*)&Cp[((size_t)b * T + t + 8) * D + d] = o;
        }
}

// mhsum: g_MH = sum of 8 AV partials (fixed order). grid = B*T*D/256.
__global__ void mhsum_kernel()
{
    const size_t i = (size_t)blockIdx.x * 256 + threadIdx.x;
    const size_t N = (size_t)B * T * D;
    float v = 0.f;
#pragma unroll
    for (int p = 0; p < 8; p++) v += g_MHp[p * N + i];
    g_MH[i] = v;
}

// ---------------------------------------------------------------------------
// Kernel 6: out = g_MH @ Wo + bo. grid = (H/64, B*T/64).
// ---------------------------------------------------------------------------
__global__ void out_kernel(const float* __restrict__ Wo,
                           const float* __restrict__ bo,
                           float* __restrict__ out)
{
    const int n0 = blockIdx.x * 64;
    const int m0 = blockIdx.y * 64;

    __shared__ float As[64][65];
    __shared__ float Bs[64][65];

    const int tx = threadIdx.x, ty = threadIdx.y;
    const int tid = ty * 16 + tx;

#pragma unroll
    for (int i = 0; i < 16; i++) {
        int idx = tid + i * 256;
        int r = idx >> 6, c = idx & 63;
        As[r][c] = g_MH[(size_t)(m0 + r) * D + c];
        Bs[r][c] = Wo[(size_t)r * H + n0 + c];
    }
    __syncthreads();

    float acc[4][4];
#pragma unroll
    for (int i = 0; i < 4; i++)
#pragma unroll
        for (int j = 0; j < 4; j++) acc[i][j] = 0.f;

#pragma unroll 8
    for (int kk = 0; kk < 64; kk++) {
        float a[4], bb[4];
#pragma unroll
        for (int i = 0; i < 4; i++) a[i]  = As[ty * 4 + i][kk];
#pragma unroll
        for (int j = 0; j < 4; j++) bb[j] = Bs[kk][tx * 4 + j];
#pragma unroll
        for (int i = 0; i < 4; i++)
#pragma unroll
            for (int j = 0; j < 4; j++) acc[i][j] += a[i] * bb[j];
    }

#pragma unroll
    for (int i = 0; i < 4; i++)
#pragma unroll
        for (int j = 0; j < 4; j++)
            out[(size_t)(m0 + ty * 4 + i) * H + n0 + tx * 4 + j] =
                acc[i][j] + bo[n0 + tx * 4 + j];
}

// ---------------------------------------------------------------------------
extern "C" void kernel_launch(void* const* d_in, const int* in_sizes, int n_in,
                              void* d_out, int out_size)
{
    const float* x  = (const float*)d_in[0];
    const float* Wq = (const float*)d_in[1];
    const float* bq = (const float*)d_in[2];
    const float* Wk = (const float*)d_in[3];
    const float* bk = (const float*)d_in[4];
    const float* Wv = (const float*)d_in[5];
    const float* bv = (const float*)d_in[6];
    const float* Wo = (const float*)d_in[7];
    const float* bo = (const float*)d_in[8];

    float* out      = (float*)d_out;                 // [B,T,H]
    float* mean_out = out + (size_t)B * T * H;       // [B,T,T]

    dim3 blk16(16, 16);

    qkproj_bf16        <<<dim3(H / 128, (B * T) / 128, 2), 256>>>(x, Wq, bq, Wk, bk);
    vproj_kernel       <<<dim3((B * T) / 64, 4), blk16>>>(x, Wv);
    vtsum_kernel       <<<(B * T) / 64, 256>>>(bv);
    scores_bf16        <<<dim3(T / 128, T / 128, NH * B), 256>>>();
    softmax_mean_kernel<<<B * T, 256>>>(mean_out);
    av_fp16            <<<dim3(T / 128, B, 8), 256>>>();
    mhsum_kernel       <<<(B * T * D) / 256, 256>>>();
    out_kernel         <<<dim3(H / 64, (B * T) / 64), blk16>>>(Wo, bo, out);
}

// round 14
// speedup vs baseline: 1.1084x; 1.0114x over previous
#include <cuda_runtime.h>
#include <cuda_fp16.h>
#include <cuda_bf16.h>
#include <math.h>
#include <stdint.h>

#define B    2
#define T    2048
#define H    1024
#define NH   16
#define D    64
#define SCALE 0.125f   // D^-0.5

#define NAVCH 16   // AV s-chunks

// ---------------- static device scratch (no dynamic allocation allowed) ----
__device__ __nv_bfloat16 g_Qh[(size_t)B * T * H];   // 8 MB
__device__ __nv_bfloat16 g_Kh[(size_t)B * T * H];   // 8 MB
__device__ float  g_Vp[(size_t)4 * B * T * D];      // 4 MB V split-K partials
__device__ __half g_Vth[(size_t)B * D * T];         // 0.5 MB V transposed fp16 [b][d][t]
__device__ __half g_Wh[(size_t)NH * B * T * T];     // 268 MB exp(score) fp16
__device__ __half g_MWh[(size_t)B * T * T];         // 16 MB mean_weights fp16 copy
__device__ float  g_RS[(size_t)NH * B * T * 16];    // 4 MB per-(row,s-tile) exp sums
__device__ float  g_MHp[(size_t)NAVCH * B * T * D]; // 16 MB AV partials
__device__ float  g_MH[(size_t)B * T * D];          // 1 MB reduced mean_head

// ---------------------------------------------------------------------------
__device__ __forceinline__ uint32_t pack_bf2(float lo, float hi) {
    __nv_bfloat162 h = __floats2bfloat162_rn(lo, hi);
    return *(uint32_t*)&h;
}

__device__ __forceinline__ void mma_bf16(float* d, const uint32_t* a, const uint32_t* b) {
    asm volatile(
        "mma.sync.aligned.m16n8k16.row.col.f32.bf16.bf16.f32 "
        "{%0,%1,%2,%3}, {%4,%5,%6,%7}, {%8,%9}, {%0,%1,%2,%3};"
        : "+f"(d[0]), "+f"(d[1]), "+f"(d[2]), "+f"(d[3])
        : "r"(a[0]), "r"(a[1]), "r"(a[2]), "r"(a[3]), "r"(b[0]), "r"(b[1]));
}

__device__ __forceinline__ void mma_fp16(float* d, const uint32_t* a, const uint32_t* b) {
    asm volatile(
        "mma.sync.aligned.m16n8k16.row.col.f32.f16.f16.f32 "
        "{%0,%1,%2,%3}, {%4,%5,%6,%7}, {%8,%9}, {%0,%1,%2,%3};"
        : "+f"(d[0]), "+f"(d[1]), "+f"(d[2]), "+f"(d[3])
        : "r"(a[0]), "r"(a[1]), "r"(a[2]), "r"(a[3]), "r"(b[0]), "r"(b[1]));
}

__device__ __forceinline__ uint32_t smem_u32(const void* p) {
    uint32_t a;
    asm("{ .reg .u64 t; cvta.to.shared.u64 t, %1; cvt.u32.u64 %0, t; }"
        : "=r"(a) : "l"(p));
    return a;
}

__device__ __forceinline__ void ldsm_x4(uint32_t* r, uint32_t addr) {
    asm volatile("ldmatrix.sync.aligned.m8n8.x4.shared.b16 {%0,%1,%2,%3}, [%4];"
        : "=r"(r[0]), "=r"(r[1]), "=r"(r[2]), "=r"(r[3]) : "r"(addr));
}

// ---------------------------------------------------------------------------
// Kernel 1: batched Q/K projection, bf16 mma (EXACT R11/R13). grid = (8,32,2).
// ---------------------------------------------------------------------------
__global__ void __launch_bounds__(256)
qkproj_bf16(const float* __restrict__ x,
            const float* __restrict__ Wq, const float* __restrict__ bq,
            const float* __restrict__ Wk, const float* __restrict__ bk)
{
    const float* Wm    = blockIdx.z ? Wk : Wq;
    const float* bias  = blockIdx.z ? bk : bq;
    __nv_bfloat16* C   = blockIdx.z ? g_Kh : g_Qh;
    const int n0 = blockIdx.x * 128;
    const int m0 = blockIdx.y * 128;

    __shared__ __align__(16) uint32_t As2[2][128][20];
    __shared__ __align__(16) uint32_t Bs2[2][16][136];

    const int tid  = threadIdx.x;
    const int lane = tid & 31;
    const int wid  = tid >> 5;
    const int wm   = wid >> 2;
    const int wn   = wid & 3;
    const int fr   = lane >> 2;
    const int fc   = lane & 3;

    const int am = tid >> 1;
    const int ak = (tid & 1) * 16;
    const float* xrow = x + (size_t)(m0 + am) * H + ak;
    const int p  = tid >> 4;
    const int nn = (tid & 15) * 8;
    const int bcol = n0 + nn;
    const size_t bbase = (size_t)(bcol >> 6) * (H * D) + (size_t)(bcol & 63);

    float acc[4][4][4];
#pragma unroll
    for (int i = 0; i < 4; i++)
#pragma unroll
        for (int j = 0; j < 4; j++)
#pragma unroll
            for (int q = 0; q < 4; q++) acc[i][j][q] = 0.f;

    float4 a0, a1, a2, a3, blo0, blo1, bhi0, bhi1;

    a0 = *(const float4*)&xrow[0];
    a1 = *(const float4*)&xrow[4];
    a2 = *(const float4*)&xrow[8];
    a3 = *(const float4*)&xrow[12];
    blo0 = *(const float4*)&Wm[bbase + (size_t)(2 * p)     * D];
    blo1 = *(const float4*)&Wm[bbase + (size_t)(2 * p)     * D + 4];
    bhi0 = *(const float4*)&Wm[bbase + (size_t)(2 * p + 1) * D];
    bhi1 = *(const float4*)&Wm[bbase + (size_t)(2 * p + 1) * D + 4];
    {
        uint4 u;
        u.x = pack_bf2(a0.x, a0.y); u.y = pack_bf2(a0.z, a0.w);
        u.z = pack_bf2(a1.x, a1.y); u.w = pack_bf2(a1.z, a1.w);
        *(uint4*)&As2[0][am][ak / 2] = u;
        u.x = pack_bf2(a2.x, a2.y); u.y = pack_bf2(a2.z, a2.w);
        u.z = pack_bf2(a3.x, a3.y); u.w = pack_bf2(a3.z, a3.w);
        *(uint4*)&As2[0][am][ak / 2 + 4] = u;
        u.x = pack_bf2(blo0.x, bhi0.x); u.y = pack_bf2(blo0.y, bhi0.y);
        u.z = pack_bf2(blo0.z, bhi0.z); u.w = pack_bf2(blo0.w, bhi0.w);
        *(uint4*)&Bs2[0][p][nn] = u;
        u.x = pack_bf2(blo1.x, bhi1.x); u.y = pack_bf2(blo1.y, bhi1.y);
        u.z = pack_bf2(blo1.z, bhi1.z); u.w = pack_bf2(blo1.w, bhi1.w);
        *(uint4*)&Bs2[0][p][nn + 4] = u;
    }
    __syncthreads();

    const int NIT = H / 32;
    for (int it = 0; it < NIT; it++) {
        const int buf = it & 1;
        if (it < NIT - 1) {
            const int k0 = (it + 1) * 32;
            a0 = *(const float4*)&xrow[k0];
            a1 = *(const float4*)&xrow[k0 + 4];
            a2 = *(const float4*)&xrow[k0 + 8];
            a3 = *(const float4*)&xrow[k0 + 12];
            blo0 = *(const float4*)&Wm[bbase + (size_t)(k0 + 2 * p)     * D];
            blo1 = *(const float4*)&Wm[bbase + (size_t)(k0 + 2 * p)     * D + 4];
            bhi0 = *(const float4*)&Wm[bbase + (size_t)(k0 + 2 * p + 1) * D];
            bhi1 = *(const float4*)&Wm[bbase + (size_t)(k0 + 2 * p + 1) * D + 4];
        }
#pragma unroll
        for (int ks = 0; ks < 2; ks++) {
            uint32_t af[4][4], bf[4][2];
#pragma unroll
            for (int tm = 0; tm < 4; tm++) {
                const int mb = wm * 64 + tm * 16;
                af[tm][0] = As2[buf][mb + fr][ks * 8 + fc];
                af[tm][1] = As2[buf][mb + fr + 8][ks * 8 + fc];
                af[tm][2] = As2[buf][mb + fr][ks * 8 + fc + 4];
                af[tm][3] = As2[buf][mb + fr + 8][ks * 8 + fc + 4];
            }
#pragma unroll
            for (int tn = 0; tn < 4; tn++) {
                const int nb = wn * 32 + tn * 8 + fr;
                bf[tn][0] = Bs2[buf][ks * 8 + fc][nb];
                bf[tn][1] = Bs2[buf][ks * 8 + fc + 4][nb];
            }
#pragma unroll
            for (int tm = 0; tm < 4; tm++)
#pragma unroll
                for (int tn = 0; tn < 4; tn++)
                    mma_bf16(acc[tm][tn], af[tm], bf[tn]);
        }
        if (it < NIT - 1) {
            const int nb2 = (it & 1) ^ 1;
            uint4 u;
            u.x = pack_bf2(a0.x, a0.y); u.y = pack_bf2(a0.z, a0.w);
            u.z = pack_bf2(a1.x, a1.y); u.w = pack_bf2(a1.z, a1.w);
            *(uint4*)&As2[nb2][am][ak / 2] = u;
            u.x = pack_bf2(a2.x, a2.y); u.y = pack_bf2(a2.z, a2.w);
            u.z = pack_bf2(a3.x, a3.y); u.w = pack_bf2(a3.z, a3.w);
            *(uint4*)&As2[nb2][am][ak / 2 + 4] = u;
            u.x = pack_bf2(blo0.x, bhi0.x); u.y = pack_bf2(blo0.y, bhi0.y);
            u.z = pack_bf2(blo0.z, bhi0.z); u.w = pack_bf2(blo0.w, bhi0.w);
            *(uint4*)&Bs2[nb2][p][nn] = u;
            u.x = pack_bf2(blo1.x, bhi1.x); u.y = pack_bf2(blo1.y, bhi1.y);
            u.z = pack_bf2(blo1.z, bhi1.z); u.w = pack_bf2(blo1.w, bhi1.w);
            *(uint4*)&Bs2[nb2][p][nn + 4] = u;
        }
        __syncthreads();
    }

#pragma unroll
    for (int tm = 0; tm < 4; tm++)
#pragma unroll
        for (int tn = 0; tn < 4; tn++) {
            const int row = m0 + wm * 64 + tm * 16 + fr;
            const int col = n0 + wn * 32 + tn * 8 + 2 * fc;
            const float b0 = bias[col], b1 = bias[col + 1];
            __nv_bfloat162 o;
            o = __floats2bfloat162_rn(acc[tm][tn][0] + b0, acc[tm][tn][1] + b1);
            *(__nv_bfloat162*)&C[(size_t)row * H + col] = o;
            o = __floats2bfloat162_rn(acc[tm][tn][2] + b0, acc[tm][tn][3] + b1);
            *(__nv_bfloat162*)&C[(size_t)(row + 8) * H + col] = o;
        }
}

// ---------------------------------------------------------------------------
// Kernel 2: V projection, split-K fp32 (EXACT R13). grid = (B*T/64, 4).
// ---------------------------------------------------------------------------
__global__ void vproj_kernel(const float* __restrict__ x,
                             const float* __restrict__ Wv)
{
    const int m0 = blockIdx.x * 64;
    const int kbase = blockIdx.y * (H / 4);
    float* Cp = g_Vp + (size_t)blockIdx.y * B * T * D;

    __shared__ float As[64][17];
    __shared__ float Bs[16][65];

    const int tx = threadIdx.x, ty = threadIdx.y;
    const int tid = ty * 16 + tx;

    float acc[4][4];
#pragma unroll
    for (int i = 0; i < 4; i++)
#pragma unroll
        for (int j = 0; j < 4; j++) acc[i][j] = 0.f;

    for (int kc = 0; kc < H / 4; kc += 16) {
        const int k0 = kbase + kc;
#pragma unroll
        for (int i = 0; i < 4; i++) {
            int idx = tid + i * 256;
            int r = idx >> 4, c = idx & 15;
            As[r][c] = x[(size_t)(m0 + r) * H + k0 + c];
        }
#pragma unroll
        for (int i = 0; i < 4; i++) {
            int idx = tid + i * 256;
            int r = idx >> 6, c = idx & 63;
            Bs[r][c] = Wv[(size_t)(k0 + r) * D + c];
        }
        __syncthreads();
#pragma unroll
        for (int kk = 0; kk < 16; kk++) {
            float a[4], bb[4];
#pragma unroll
            for (int i = 0; i < 4; i++) a[i]  = As[ty * 4 + i][kk];
#pragma unroll
            for (int j = 0; j < 4; j++) bb[j] = Bs[kk][tx * 4 + j];
#pragma unroll
            for (int i = 0; i < 4; i++)
#pragma unroll
                for (int j = 0; j < 4; j++) acc[i][j] += a[i] * bb[j];
        }
        __syncthreads();
    }
#pragma unroll
    for (int i = 0; i < 4; i++)
#pragma unroll
        for (int j = 0; j < 4; j++)
            Cp[(size_t)(m0 + ty * 4 + i) * D + tx * 4 + j] = acc[i][j];
}

// vtsum: sum 4 partials + bias, write transposed fp16 g_Vth. grid = B*T/64.
__global__ void vtsum_kernel(const float* __restrict__ bv)
{
    __shared__ float tile[64][65];
    const int m0 = blockIdx.x * 64;
    const int b  = m0 >> 11;
    const int t0 = m0 & 2047;
    const int tid = threadIdx.x;
    const size_t N = (size_t)B * T * D;

#pragma unroll
    for (int i = 0; i < 16; i++) {
        const int idx = tid + i * 256;
        const int r = idx >> 6, c = idx & 63;
        const size_t mi = (size_t)(m0 + r) * D + c;
        tile[r][c] = g_Vp[mi] + g_Vp[N + mi] + g_Vp[2 * N + mi]
                   + g_Vp[3 * N + mi] + bv[c];
    }
    __syncthreads();
#pragma unroll
    for (int i = 0; i < 16; i++) {
        const int idx = tid + i * 256;
        const int d = idx >> 6, tc = idx & 63;
        g_Vth[((size_t)b * D + d) * T + t0 + tc] = __float2half(tile[tc][d]);
    }
}

// ---------------------------------------------------------------------------
// Kernel 3: scores via bf16 mma + ldmatrix (EXACT R13). grid = (16,16,NH*B).
// ---------------------------------------------------------------------------
__global__ void __launch_bounds__(256)
scores_bf16()
{
    const int st = blockIdx.x;
    const int tt = blockIdx.y;
    if (st > tt) return;
    const int z = blockIdx.z;
    const int n = z >> 1, b = z & 1;

    const __nv_bfloat16* Qb = g_Qh + (size_t)b * T * H + (size_t)n * D;
    const __nv_bfloat16* Kb = g_Kh + (size_t)b * T * H + (size_t)n * D;
    __half* Wp = g_Wh + (size_t)z * T * T;

    const int t0 = tt * 128, s0 = st * 128;

    __shared__ __align__(16) union {
        struct { uint32_t Q[128][36]; uint32_t K[128][36]; } qk;
        uint32_t S[128][68];
    } sm;
    __shared__ float rs[128][4];

    const int tid  = threadIdx.x;
    const int lane = tid & 31;
    const int wid  = tid >> 5;
    const int wm   = wid >> 2;
    const int wn   = wid & 3;
    const int fr   = lane >> 2;
    const int fc   = lane & 3;

    const int sr = tid >> 1;
    const int sc = (tid & 1) * 32;
#pragma unroll
    for (int u = 0; u < 4; u++) {
        uint4 q4 = *(const uint4*)&Qb[(size_t)(t0 + sr) * H + sc + u * 8];
        uint4 k4 = *(const uint4*)&Kb[(size_t)(s0 + sr) * H + sc + u * 8];
        *(uint4*)&sm.qk.Q[sr][sc / 2 + u * 4] = q4;
        *(uint4*)&sm.qk.K[sr][sc / 2 + u * 4] = k4;
    }
    __syncthreads();

    uint32_t aAddr[4];
    {
        const int lr = lane & 15, lk = (lane >> 4) * 4;
#pragma unroll
        for (int tm = 0; tm < 4; tm++)
            aAddr[tm] = smem_u32(&sm.qk.Q[wm * 64 + tm * 16 + lr][lk]);
    }
    uint32_t bAddr[2];
    {
        const int br = (lane >> 4) * 8 + (lane & 7);
        const int bk = ((lane >> 3) & 1) * 4;
#pragma unroll
        for (int tp = 0; tp < 2; tp++)
            bAddr[tp] = smem_u32(&sm.qk.K[wn * 32 + tp * 16 + br][bk]);
    }

    float acc[4][4][4];
#pragma unroll
    for (int i = 0; i < 4; i++)
#pragma unroll
        for (int j = 0; j < 4; j++)
#pragma unroll
            for (int q = 0; q < 4; q++) acc[i][j][q] = 0.f;

#pragma unroll
    for (int ks = 0; ks < 4; ks++) {
        uint32_t af[4][4], bq0[4], bq1[4];
#pragma unroll
        for (int tm = 0; tm < 4; tm++)
            ldsm_x4(af[tm], aAddr[tm] + ks * 32);
        ldsm_x4(bq0, bAddr[0] + ks * 32);
        ldsm_x4(bq1, bAddr[1] + ks * 32);
        uint32_t bf[4][2];
        bf[0][0] = bq0[0]; bf[0][1] = bq0[1];
        bf[1][0] = bq0[2]; bf[1][1] = bq0[3];
        bf[2][0] = bq1[0]; bf[2][1] = bq1[1];
        bf[3][0] = bq1[2]; bf[3][1] = bq1[3];
#pragma unroll
        for (int tm = 0; tm < 4; tm++)
#pragma unroll
            for (int tn = 0; tn < 4; tn++)
                mma_bf16(acc[tm][tn], af[tm], bf[tn]);
    }

    __syncthreads();

    const bool diag = (st == tt);
#pragma unroll
    for (int tm = 0; tm < 4; tm++)
#pragma unroll
        for (int rq = 0; rq < 2; rq++) {
            const int rloc = wm * 64 + tm * 16 + fr + rq * 8;
            const int t = t0 + rloc;
            float rsum = 0.f;
#pragma unroll
            for (int tn = 0; tn < 4; tn++) {
                const int s = s0 + wn * 32 + tn * 8 + 2 * fc;
                float e0 = __expf(acc[tm][tn][rq * 2 + 0] * SCALE);
                float e1 = __expf(acc[tm][tn][rq * 2 + 1] * SCALE);
                if (diag) {
                    if (s     > t) e0 = 0.f;
                    if (s + 1 > t) e1 = 0.f;
                }
                rsum += e0 + e1;
                __half2 h = __floats2half2_rn(e0, e1);
                sm.S[rloc][wn * 16 + tn * 4 + fc] = *(uint32_t*)&h;
            }
            rsum += __shfl_xor_sync(0xffffffffu, rsum, 1);
            rsum += __shfl_xor_sync(0xffffffffu, rsum, 2);
            if (fc == 0) rs[rloc][wn] = rsum;
        }
    __syncthreads();

    if (tid < 128) {
        float v = rs[tid][0] + rs[tid][1] + rs[tid][2] + rs[tid][3];
        g_RS[((size_t)z * T + t0 + tid) * 16 + st] = v;
    }

    const int rr0 = tid >> 4;
    const int cw  = (tid & 15) * 4;
#pragma unroll
    for (int i = 0; i < 8; i++) {
        const int rr = rr0 + i * 16;
        uint4 v = *(const uint4*)&sm.S[rr][cw];
        *(uint4*)&Wp[(size_t)(t0 + rr) * T + s0 + cw * 2] = v;
    }
}

// ---------------------------------------------------------------------------
// Kernel 4: streaming mean-of-softmax; fp32 output + fp16 copy (EXACT R13).
// ---------------------------------------------------------------------------
__global__ void __launch_bounds__(256)
softmax_mean_kernel(float* __restrict__ out_mean)
{
    const int row = (B * T - 1) - blockIdx.x;
    const int b = row >> 11;
    const int t = row & 2047;
    const int tid = threadIdx.x;

    const int nst = (t >> 7) + 1;
    const int L   = nst * 128;

    __shared__ float sinv[NH];
    if (tid < NH) {
        const float* p = g_RS + ((size_t)(tid * B + b) * T + t) * 16;
        float s = 0.f;
        for (int i = 0; i < nst; i++) s += p[i];
        sinv[tid] = (1.0f / NH) / s;
    }
    __syncthreads();

    const int c0 = tid * 8;
    float acc[8];
#pragma unroll
    for (int i = 0; i < 8; i++) acc[i] = 0.f;

    if (c0 < L) {
        const size_t rowoff = ((size_t)b * T + t) * T + c0;
#pragma unroll
        for (int n = 0; n < NH; n++) {
            const __half* p = g_Wh + (size_t)n * (B * (size_t)T * T) + rowoff;
            uint4 u = *(const uint4*)p;
            const float w = sinv[n];
            float2 f;
            f = __half22float2(*(__half2*)&u.x); acc[0] += f.x * w; acc[1] += f.y * w;
            f = __half22float2(*((__half2*)&u.x + 1)); acc[2] += f.x * w; acc[3] += f.y * w;
            f = __half22float2(*(__half2*)&u.z); acc[4] += f.x * w; acc[5] += f.y * w;
            f = __half22float2(*((__half2*)&u.z + 1)); acc[6] += f.x * w; acc[7] += f.y * w;
        }
    }

    float* mrow = out_mean + (size_t)row * T + c0;
    *(float4*)&mrow[0] = make_float4(acc[0], acc[1], acc[2], acc[3]);
    *(float4*)&mrow[4] = make_float4(acc[4], acc[5], acc[6], acc[7]);

    uint4 hq;
    __half2 h;
    h = __floats2half2_rn(acc[0], acc[1]); hq.x = *(uint32_t*)&h;
    h = __floats2half2_rn(acc[2], acc[3]); hq.y = *(uint32_t*)&h;
    h = __floats2half2_rn(acc[4], acc[5]); hq.z = *(uint32_t*)&h;
    h = __floats2half2_rn(acc[6], acc[7]); hq.w = *(uint32_t*)&h;
    *(uint4*)&g_MWh[(size_t)row * T + c0] = hq;
}

// ---------------------------------------------------------------------------
// Kernel 5: AV via fp16 mma + ldmatrix, 16 s-chunks. grid = (16, B, 16).
// ---------------------------------------------------------------------------
__global__ void __launch_bounds__(256)
av_fp16()
{
    const int tt    = blockIdx.x;
    const int b     = blockIdx.y;
    const int chunk = blockIdx.z;
    const int t0 = tt * 128;

    const int st_begin = chunk * 2;
    const int st_end   = min(chunk * 2 + 2, ((t0 + 127) >> 6) + 1);

    __shared__ __align__(16) uint32_t Aw[128][36];
    __shared__ __align__(16) uint32_t Bw[64][36];

    const int tid  = threadIdx.x;
    const int lane = tid & 31;
    const int wid  = tid >> 5;
    const int wm   = wid >> 1;
    const int wn   = wid & 1;
    const int fr   = lane >> 2;
    const int fc   = lane & 3;

    const int asr = tid >> 1;
    const int asc = (tid & 1) * 32;
    const int bsr = tid >> 2;
    const int bsc = (tid & 3) * 16;

    uint32_t aAddr[2];
    {
        const int lr = lane & 15, lk = (lane >> 4) * 4;
#pragma unroll
        for (int tm = 0; tm < 2; tm++)
            aAddr[tm] = smem_u32(&Aw[wm * 32 + tm * 16 + lr][lk]);
    }
    uint32_t bAddr[2];
    {
        const int br = (lane >> 4) * 8 + (lane & 7);
        const int bk = ((lane >> 3) & 1) * 4;
#pragma unroll
        for (int tp = 0; tp < 2; tp++)
            bAddr[tp] = smem_u32(&Bw[wn * 32 + tp * 16 + br][bk]);
    }

    float acc[2][4][4];
#pragma unroll
    for (int i = 0; i < 2; i++)
#pragma unroll
        for (int j = 0; j < 4; j++)
#pragma unroll
            for (int q = 0; q < 4; q++) acc[i][j][q] = 0.f;

    for (int st = st_begin; st < st_end; st++) {
        const int s0 = st * 64;
        if (st > st_begin) __syncthreads();
        {
            const __half* src = g_MWh + ((size_t)b * T + t0 + asr) * T + s0 + asc;
#pragma unroll
            for (int u = 0; u < 4; u++)
                *(uint4*)&Aw[asr][asc / 2 + u * 4] = *(const uint4*)&src[u * 8];
        }
        {
            const __half* src = g_Vth + ((size_t)b * D + bsr) * T + s0 + bsc;
#pragma unroll
            for (int u = 0; u < 2; u++)
                *(uint4*)&Bw[bsr][bsc / 2 + u * 4] = *(const uint4*)&src[u * 8];
        }
        __syncthreads();

#pragma unroll
        for (int ks = 0; ks < 4; ks++) {
            uint32_t af[2][4], bq0[4], bq1[4];
#pragma unroll
            for (int tm = 0; tm < 2; tm++)
                ldsm_x4(af[tm], aAddr[tm] + ks * 32);
            ldsm_x4(bq0, bAddr[0] + ks * 32);
            ldsm_x4(bq1, bAddr[1] + ks * 32);
            uint32_t bf[4][2];
            bf[0][0] = bq0[0]; bf[0][1] = bq0[1];
            bf[1][0] = bq0[2]; bf[1][1] = bq0[3];
            bf[2][0] = bq1[0]; bf[2][1] = bq1[1];
            bf[3][0] = bq1[2]; bf[3][1] = bq1[3];
#pragma unroll
            for (int tm = 0; tm < 2; tm++)
#pragma unroll
                for (int tn = 0; tn < 4; tn++)
                    mma_fp16(acc[tm][tn], af[tm], bf[tn]);
        }
    }

    float* Cp = g_MHp + (size_t)chunk * B * T * D;
#pragma unroll
    for (int tm = 0; tm < 2; tm++)
#pragma unroll
        for (int tn = 0; tn < 4; tn++) {
            const int t = t0 + wm * 32 + tm * 16 + fr;
            const int d = wn * 32 + tn * 8 + 2 * fc;
            float2 o;
            o.x = acc[tm][tn][0]; o.y = acc[tm][tn][1];
            *(float2*)&Cp[((size_t)b * T + t) * D + d] = o;
            o.x = acc[tm][tn][2]; o.y = acc[tm][tn][3];
            *(float2*)&Cp[((size_t)b * T + t + 8) * D + d] = o;
        }
}

// mhsum: g_MH = sum of NAVCH AV partials (fixed order). grid = B*T*D/256.
__global__ void mhsum_kernel()
{
    const size_t i = (size_t)blockIdx.x * 256 + threadIdx.x;
    const size_t N = (size_t)B * T * D;
    float v = 0.f;
#pragma unroll
    for (int p = 0; p < NAVCH; p++) v += g_MHp[p * N + i];
    g_MH[i] = v;
}

// ---------------------------------------------------------------------------
// Kernel 6: out = g_MH @ Wo + bo. grid = (H/64, B*T/64).
// ---------------------------------------------------------------------------
__global__ void out_kernel(const float* __restrict__ Wo,
                           const float* __restrict__ bo,
                           float* __restrict__ out)
{
    const int n0 = blockIdx.x * 64;
    const int m0 = blockIdx.y * 64;

    __shared__ float As[64][65];
    __shared__ float Bs[64][65];

    const int tx = threadIdx.x, ty = threadIdx.y;
    const int tid = ty * 16 + tx;

#pragma unroll
    for (int i = 0; i < 16; i++) {
        int idx = tid + i * 256;
        int r = idx >> 6, c = idx & 63;
        As[r][c] = g_MH[(size_t)(m0 + r) * D + c];
        Bs[r][c] = Wo[(size_t)r * H + n0 + c];
    }
    __syncthreads();

    float acc[4][4];
#pragma unroll
    for (int i = 0; i < 4; i++)
#pragma unroll
        for (int j = 0; j < 4; j++) acc[i][j] = 0.f;

#pragma unroll 8
    for (int kk = 0; kk < 64; kk++) {
        float a[4], bb[4];
#pragma unroll
        for (int i = 0; i < 4; i++) a[i]  = As[ty * 4 + i][kk];
#pragma unroll
        for (int j = 0; j < 4; j++) bb[j] = Bs[kk][tx * 4 + j];
#pragma unroll
        for (int i = 0; i < 4; i++)
#pragma unroll
            for (int j = 0; j < 4; j++) acc[i][j] += a[i] * bb[j];
    }

#pragma unroll
    for (int i = 0; i < 4; i++)
#pragma unroll
        for (int j = 0; j < 4; j++)
            out[(size_t)(m0 + ty * 4 + i) * H + n0 + tx * 4 + j] =
                acc[i][j] + bo[n0 + tx * 4 + j];
}

// ---------------------------------------------------------------------------
extern "C" void kernel_launch(void* const* d_in, const int* in_sizes, int n_in,
                              void* d_out, int out_size)
{
    const float* x  = (const float*)d_in[0];
    const float* Wq = (const float*)d_in[1];
    const float* bq = (const float*)d_in[2];
    const float* Wk = (const float*)d_in[3];
    const float* bk = (const float*)d_in[4];
    const float* Wv = (const float*)d_in[5];
    const float* bv = (const float*)d_in[6];
    const float* Wo = (const float*)d_in[7];
    const float* bo = (const float*)d_in[8];

    float* out      = (float*)d_out;                 // [B,T,H]
    float* mean_out = out + (size_t)B * T * H;       // [B,T,T]

    dim3 blk16(16, 16);

    // Lazily created host-side stream/events (no device memory allocation;
    // same work on every call -> deterministic & graph-capturable).
    static cudaStream_t s_v = nullptr;
    static cudaEvent_t  ev_fork = nullptr, ev_join = nullptr;
    if (s_v == nullptr) {
        cudaStreamCreateWithFlags(&s_v, cudaStreamNonBlocking);
        cudaEventCreateWithFlags(&ev_fork, cudaEventDisableTiming);
        cudaEventCreateWithFlags(&ev_join, cudaEventDisableTiming);
    }

    // fork: V path runs concurrently with Q/K projection + scores
    cudaEventRecord(ev_fork, 0);
    cudaStreamWaitEvent(s_v, ev_fork, 0);
    vproj_kernel <<<dim3((B * T) / 64, 4), blk16, 0, s_v>>>(x, Wv);
    vtsum_kernel <<<(B * T) / 64, 256, 0, s_v>>>(bv);
    cudaEventRecord(ev_join, s_v);

    qkproj_bf16        <<<dim3(H / 128, (B * T) / 128, 2), 256>>>(x, Wq, bq, Wk, bk);
    scores_bf16        <<<dim3(T / 128, T / 128, NH * B), 256>>>();
    softmax_mean_kernel<<<B * T, 256>>>(mean_out);

    // join: av needs g_Vth
    cudaStreamWaitEvent(0, ev_join, 0);
    av_fp16            <<<dim3(T / 128, B, NAVCH), 256>>>();
    mhsum_kernel       <<<(B * T * D) / 256, 256>>>();
    out_kernel         <<<dim3(H / 64, (B * T) / 64), blk16>>>(Wo, bo, out);
}

// round 15
// speedup vs baseline: 1.1145x; 1.0056x over previous
#include <cuda_runtime.h>
#include <cuda_fp16.h>
#include <cuda_bf16.h>
#include <math.h>
#include <stdint.h>

#define B    2
#define T    2048
#define H    1024
#define NH   16
#define D    64
#define SCALE 0.125f   // D^-0.5

#define NAVCH 16   // AV s-chunks

// ---------------- static device scratch (no dynamic allocation allowed) ----
__device__ __nv_bfloat16 g_Qh[(size_t)B * T * H];   // 8 MB
__device__ __nv_bfloat16 g_Kh[(size_t)B * T * H];   // 8 MB
__device__ float  g_Vp[(size_t)4 * B * T * D];      // 4 MB V split-K partials
__device__ __half g_Vth[(size_t)B * D * T];         // 0.5 MB V transposed fp16 [b][d][t]
__device__ __half g_Wh[(size_t)NH * B * T * T];     // 268 MB exp(score) fp16
__device__ __half g_MWh[(size_t)B * T * T];         // 16 MB mean_weights fp16 copy
__device__ float  g_RS[(size_t)NH * B * T * 16];    // 4 MB per-(row,s-tile) exp sums
__device__ float  g_MHp[(size_t)NAVCH * B * T * D]; // 16 MB AV partials
__device__ float  g_MH[(size_t)B * T * D];          // 1 MB reduced mean_head

// ---------------------------------------------------------------------------
__device__ __forceinline__ uint32_t pack_bf2(float lo, float hi) {
    __nv_bfloat162 h = __floats2bfloat162_rn(lo, hi);
    return *(uint32_t*)&h;
}

__device__ __forceinline__ void mma_bf16(float* d, const uint32_t* a, const uint32_t* b) {
    asm volatile(
        "mma.sync.aligned.m16n8k16.row.col.f32.bf16.bf16.f32 "
        "{%0,%1,%2,%3}, {%4,%5,%6,%7}, {%8,%9}, {%0,%1,%2,%3};"
        : "+f"(d[0]), "+f"(d[1]), "+f"(d[2]), "+f"(d[3])
        : "r"(a[0]), "r"(a[1]), "r"(a[2]), "r"(a[3]), "r"(b[0]), "r"(b[1]));
}

__device__ __forceinline__ void mma_fp16(float* d, const uint32_t* a, const uint32_t* b) {
    asm volatile(
        "mma.sync.aligned.m16n8k16.row.col.f32.f16.f16.f32 "
        "{%0,%1,%2,%3}, {%4,%5,%6,%7}, {%8,%9}, {%0,%1,%2,%3};"
        : "+f"(d[0]), "+f"(d[1]), "+f"(d[2]), "+f"(d[3])
        : "r"(a[0]), "r"(a[1]), "r"(a[2]), "r"(a[3]), "r"(b[0]), "r"(b[1]));
}

__device__ __forceinline__ uint32_t smem_u32(const void* p) {
    uint32_t a;
    asm("{ .reg .u64 t; cvta.to.shared.u64 t, %1; cvt.u32.u64 %0, t; }"
        : "=r"(a) : "l"(p));
    return a;
}

__device__ __forceinline__ void ldsm_x4(uint32_t* r, uint32_t addr) {
    asm volatile("ldmatrix.sync.aligned.m8n8.x4.shared.b16 {%0,%1,%2,%3}, [%4];"
        : "=r"(r[0]), "=r"(r[1]), "=r"(r[2]), "=r"(r[3]) : "r"(addr));
}

// ---------------------------------------------------------------------------
// Kernel 1: batched Q/K projection, bf16 mma (EXACT R13/R14). grid = (8,32,2).
// ---------------------------------------------------------------------------
__global__ void __launch_bounds__(256)
qkproj_bf16(const float* __restrict__ x,
            const float* __restrict__ Wq, const float* __restrict__ bq,
            const float* __restrict__ Wk, const float* __restrict__ bk)
{
    const float* Wm    = blockIdx.z ? Wk : Wq;
    const float* bias  = blockIdx.z ? bk : bq;
    __nv_bfloat16* C   = blockIdx.z ? g_Kh : g_Qh;
    const int n0 = blockIdx.x * 128;
    const int m0 = blockIdx.y * 128;

    __shared__ __align__(16) uint32_t As2[2][128][20];
    __shared__ __align__(16) uint32_t Bs2[2][16][136];

    const int tid  = threadIdx.x;
    const int lane = tid & 31;
    const int wid  = tid >> 5;
    const int wm   = wid >> 2;
    const int wn   = wid & 3;
    const int fr   = lane >> 2;
    const int fc   = lane & 3;

    const int am = tid >> 1;
    const int ak = (tid & 1) * 16;
    const float* xrow = x + (size_t)(m0 + am) * H + ak;
    const int p  = tid >> 4;
    const int nn = (tid & 15) * 8;
    const int bcol = n0 + nn;
    const size_t bbase = (size_t)(bcol >> 6) * (H * D) + (size_t)(bcol & 63);

    float acc[4][4][4];
#pragma unroll
    for (int i = 0; i < 4; i++)
#pragma unroll
        for (int j = 0; j < 4; j++)
#pragma unroll
            for (int q = 0; q < 4; q++) acc[i][j][q] = 0.f;

    float4 a0, a1, a2, a3, blo0, blo1, bhi0, bhi1;

    a0 = *(const float4*)&xrow[0];
    a1 = *(const float4*)&xrow[4];
    a2 = *(const float4*)&xrow[8];
    a3 = *(const float4*)&xrow[12];
    blo0 = *(const float4*)&Wm[bbase + (size_t)(2 * p)     * D];
    blo1 = *(const float4*)&Wm[bbase + (size_t)(2 * p)     * D + 4];
    bhi0 = *(const float4*)&Wm[bbase + (size_t)(2 * p + 1) * D];
    bhi1 = *(const float4*)&Wm[bbase + (size_t)(2 * p + 1) * D + 4];
    {
        uint4 u;
        u.x = pack_bf2(a0.x, a0.y); u.y = pack_bf2(a0.z, a0.w);
        u.z = pack_bf2(a1.x, a1.y); u.w = pack_bf2(a1.z, a1.w);
        *(uint4*)&As2[0][am][ak / 2] = u;
        u.x = pack_bf2(a2.x, a2.y); u.y = pack_bf2(a2.z, a2.w);
        u.z = pack_bf2(a3.x, a3.y); u.w = pack_bf2(a3.z, a3.w);
        *(uint4*)&As2[0][am][ak / 2 + 4] = u;
        u.x = pack_bf2(blo0.x, bhi0.x); u.y = pack_bf2(blo0.y, bhi0.y);
        u.z = pack_bf2(blo0.z, bhi0.z); u.w = pack_bf2(blo0.w, bhi0.w);
        *(uint4*)&Bs2[0][p][nn] = u;
        u.x = pack_bf2(blo1.x, bhi1.x); u.y = pack_bf2(blo1.y, bhi1.y);
        u.z = pack_bf2(blo1.z, bhi1.z); u.w = pack_bf2(blo1.w, bhi1.w);
        *(uint4*)&Bs2[0][p][nn + 4] = u;
    }
    __syncthreads();

    const int NIT = H / 32;
    for (int it = 0; it < NIT; it++) {
        const int buf = it & 1;
        if (it < NIT - 1) {
            const int k0 = (it + 1) * 32;
            a0 = *(const float4*)&xrow[k0];
            a1 = *(const float4*)&xrow[k0 + 4];
            a2 = *(const float4*)&xrow[k0 + 8];
            a3 = *(const float4*)&xrow[k0 + 12];
            blo0 = *(const float4*)&Wm[bbase + (size_t)(k0 + 2 * p)     * D];
            blo1 = *(const float4*)&Wm[bbase + (size_t)(k0 + 2 * p)     * D + 4];
            bhi0 = *(const float4*)&Wm[bbase + (size_t)(k0 + 2 * p + 1) * D];
            bhi1 = *(const float4*)&Wm[bbase + (size_t)(k0 + 2 * p + 1) * D + 4];
        }
#pragma unroll
        for (int ks = 0; ks < 2; ks++) {
            uint32_t af[4][4], bf[4][2];
#pragma unroll
            for (int tm = 0; tm < 4; tm++) {
                const int mb = wm * 64 + tm * 16;
                af[tm][0] = As2[buf][mb + fr][ks * 8 + fc];
                af[tm][1] = As2[buf][mb + fr + 8][ks * 8 + fc];
                af[tm][2] = As2[buf][mb + fr][ks * 8 + fc + 4];
                af[tm][3] = As2[buf][mb + fr + 8][ks * 8 + fc + 4];
            }
#pragma unroll
            for (int tn = 0; tn < 4; tn++) {
                const int nb = wn * 32 + tn * 8 + fr;
                bf[tn][0] = Bs2[buf][ks * 8 + fc][nb];
                bf[tn][1] = Bs2[buf][ks * 8 + fc + 4][nb];
            }
#pragma unroll
            for (int tm = 0; tm < 4; tm++)
#pragma unroll
                for (int tn = 0; tn < 4; tn++)
                    mma_bf16(acc[tm][tn], af[tm], bf[tn]);
        }
        if (it < NIT - 1) {
            const int nb2 = (it & 1) ^ 1;
            uint4 u;
            u.x = pack_bf2(a0.x, a0.y); u.y = pack_bf2(a0.z, a0.w);
            u.z = pack_bf2(a1.x, a1.y); u.w = pack_bf2(a1.z, a1.w);
            *(uint4*)&As2[nb2][am][ak / 2] = u;
            u.x = pack_bf2(a2.x, a2.y); u.y = pack_bf2(a2.z, a2.w);
            u.z = pack_bf2(a3.x, a3.y); u.w = pack_bf2(a3.z, a3.w);
            *(uint4*)&As2[nb2][am][ak / 2 + 4] = u;
            u.x = pack_bf2(blo0.x, bhi0.x); u.y = pack_bf2(blo0.y, bhi0.y);
            u.z = pack_bf2(blo0.z, bhi0.z); u.w = pack_bf2(blo0.w, bhi0.w);
            *(uint4*)&Bs2[nb2][p][nn] = u;
            u.x = pack_bf2(blo1.x, bhi1.x); u.y = pack_bf2(blo1.y, bhi1.y);
            u.z = pack_bf2(blo1.z, bhi1.z); u.w = pack_bf2(blo1.w, bhi1.w);
            *(uint4*)&Bs2[nb2][p][nn + 4] = u;
        }
        __syncthreads();
    }

#pragma unroll
    for (int tm = 0; tm < 4; tm++)
#pragma unroll
        for (int tn = 0; tn < 4; tn++) {
            const int row = m0 + wm * 64 + tm * 16 + fr;
            const int col = n0 + wn * 32 + tn * 8 + 2 * fc;
            const float b0 = bias[col], b1 = bias[col + 1];
            __nv_bfloat162 o;
            o = __floats2bfloat162_rn(acc[tm][tn][0] + b0, acc[tm][tn][1] + b1);
            *(__nv_bfloat162*)&C[(size_t)row * H + col] = o;
            o = __floats2bfloat162_rn(acc[tm][tn][2] + b0, acc[tm][tn][3] + b1);
            *(__nv_bfloat162*)&C[(size_t)(row + 8) * H + col] = o;
        }
}

// ---------------------------------------------------------------------------
// Kernel 2: V projection, split-K fp32 (EXACT R13/R14). grid = (B*T/64, 4).
// ---------------------------------------------------------------------------
__global__ void vproj_kernel(const float* __restrict__ x,
                             const float* __restrict__ Wv)
{
    const int m0 = blockIdx.x * 64;
    const int kbase = blockIdx.y * (H / 4);
    float* Cp = g_Vp + (size_t)blockIdx.y * B * T * D;

    __shared__ float As[64][17];
    __shared__ float Bs[16][65];

    const int tx = threadIdx.x, ty = threadIdx.y;
    const int tid = ty * 16 + tx;

    float acc[4][4];
#pragma unroll
    for (int i = 0; i < 4; i++)
#pragma unroll
        for (int j = 0; j < 4; j++) acc[i][j] = 0.f;

    for (int kc = 0; kc < H / 4; kc += 16) {
        const int k0 = kbase + kc;
#pragma unroll
        for (int i = 0; i < 4; i++) {
            int idx = tid + i * 256;
            int r = idx >> 4, c = idx & 15;
            As[r][c] = x[(size_t)(m0 + r) * H + k0 + c];
        }
#pragma unroll
        for (int i = 0; i < 4; i++) {
            int idx = tid + i * 256;
            int r = idx >> 6, c = idx & 63;
            Bs[r][c] = Wv[(size_t)(k0 + r) * D + c];
        }
        __syncthreads();
#pragma unroll
        for (int kk = 0; kk < 16; kk++) {
            float a[4], bb[4];
#pragma unroll
            for (int i = 0; i < 4; i++) a[i]  = As[ty * 4 + i][kk];
#pragma unroll
            for (int j = 0; j < 4; j++) bb[j] = Bs[kk][tx * 4 + j];
#pragma unroll
            for (int i = 0; i < 4; i++)
#pragma unroll
                for (int j = 0; j < 4; j++) acc[i][j] += a[i] * bb[j];
        }
        __syncthreads();
    }
#pragma unroll
    for (int i = 0; i < 4; i++)
#pragma unroll
        for (int j = 0; j < 4; j++)
            Cp[(size_t)(m0 + ty * 4 + i) * D + tx * 4 + j] = acc[i][j];
}

// vtsum: sum 4 partials + bias, write transposed fp16 g_Vth. grid = B*T/64.
__global__ void vtsum_kernel(const float* __restrict__ bv)
{
    __shared__ float tile[64][65];
    const int m0 = blockIdx.x * 64;
    const int b  = m0 >> 11;
    const int t0 = m0 & 2047;
    const int tid = threadIdx.x;
    const size_t N = (size_t)B * T * D;

#pragma unroll
    for (int i = 0; i < 16; i++) {
        const int idx = tid + i * 256;
        const int r = idx >> 6, c = idx & 63;
        const size_t mi = (size_t)(m0 + r) * D + c;
        tile[r][c] = g_Vp[mi] + g_Vp[N + mi] + g_Vp[2 * N + mi]
                   + g_Vp[3 * N + mi] + bv[c];
    }
    __syncthreads();
#pragma unroll
    for (int i = 0; i < 16; i++) {
        const int idx = tid + i * 256;
        const int d = idx >> 6, tc = idx & 63;
        g_Vth[((size_t)b * D + d) * T + t0 + tc] = __float2half(tile[tc][d]);
    }
}

// ---------------------------------------------------------------------------
// Kernel 3: scores via bf16 mma + ldmatrix (EXACT R13/R14). grid=(16,16,NH*B).
// ---------------------------------------------------------------------------
__global__ void __launch_bounds__(256)
scores_bf16()
{
    const int st = blockIdx.x;
    const int tt = blockIdx.y;
    if (st > tt) return;
    const int z = blockIdx.z;
    const int n = z >> 1, b = z & 1;

    const __nv_bfloat16* Qb = g_Qh + (size_t)b * T * H + (size_t)n * D;
    const __nv_bfloat16* Kb = g_Kh + (size_t)b * T * H + (size_t)n * D;
    __half* Wp = g_Wh + (size_t)z * T * T;

    const int t0 = tt * 128, s0 = st * 128;

    __shared__ __align__(16) union {
        struct { uint32_t Q[128][36]; uint32_t K[128][36]; } qk;
        uint32_t S[128][68];
    } sm;
    __shared__ float rs[128][4];

    const int tid  = threadIdx.x;
    const int lane = tid & 31;
    const int wid  = tid >> 5;
    const int wm   = wid >> 2;
    const int wn   = wid & 3;
    const int fr   = lane >> 2;
    const int fc   = lane & 3;

    const int sr = tid >> 1;
    const int sc = (tid & 1) * 32;
#pragma unroll
    for (int u = 0; u < 4; u++) {
        uint4 q4 = *(const uint4*)&Qb[(size_t)(t0 + sr) * H + sc + u * 8];
        uint4 k4 = *(const uint4*)&Kb[(size_t)(s0 + sr) * H + sc + u * 8];
        *(uint4*)&sm.qk.Q[sr][sc / 2 + u * 4] = q4;
        *(uint4*)&sm.qk.K[sr][sc / 2 + u * 4] = k4;
    }
    __syncthreads();

    uint32_t aAddr[4];
    {
        const int lr = lane & 15, lk = (lane >> 4) * 4;
#pragma unroll
        for (int tm = 0; tm < 4; tm++)
            aAddr[tm] = smem_u32(&sm.qk.Q[wm * 64 + tm * 16 + lr][lk]);
    }
    uint32_t bAddr[2];
    {
        const int br = (lane >> 4) * 8 + (lane & 7);
        const int bk = ((lane >> 3) & 1) * 4;
#pragma unroll
        for (int tp = 0; tp < 2; tp++)
            bAddr[tp] = smem_u32(&sm.qk.K[wn * 32 + tp * 16 + br][bk]);
    }

    float acc[4][4][4];
#pragma unroll
    for (int i = 0; i < 4; i++)
#pragma unroll
        for (int j = 0; j < 4; j++)
#pragma unroll
            for (int q = 0; q < 4; q++) acc[i][j][q] = 0.f;

#pragma unroll
    for (int ks = 0; ks < 4; ks++) {
        uint32_t af[4][4], bq0[4], bq1[4];
#pragma unroll
        for (int tm = 0; tm < 4; tm++)
            ldsm_x4(af[tm], aAddr[tm] + ks * 32);
        ldsm_x4(bq0, bAddr[0] + ks * 32);
        ldsm_x4(bq1, bAddr[1] + ks * 32);
        uint32_t bf[4][2];
        bf[0][0] = bq0[0]; bf[0][1] = bq0[1];
        bf[1][0] = bq0[2]; bf[1][1] = bq0[3];
        bf[2][0] = bq1[0]; bf[2][1] = bq1[1];
        bf[3][0] = bq1[2]; bf[3][1] = bq1[3];
#pragma unroll
        for (int tm = 0; tm < 4; tm++)
#pragma unroll
            for (int tn = 0; tn < 4; tn++)
                mma_bf16(acc[tm][tn], af[tm], bf[tn]);
    }

    __syncthreads();

    const bool diag = (st == tt);
#pragma unroll
    for (int tm = 0; tm < 4; tm++)
#pragma unroll
        for (int rq = 0; rq < 2; rq++) {
            const int rloc = wm * 64 + tm * 16 + fr + rq * 8;
            const int t = t0 + rloc;
            float rsum = 0.f;
#pragma unroll
            for (int tn = 0; tn < 4; tn++) {
                const int s = s0 + wn * 32 + tn * 8 + 2 * fc;
                float e0 = __expf(acc[tm][tn][rq * 2 + 0] * SCALE);
                float e1 = __expf(acc[tm][tn][rq * 2 + 1] * SCALE);
                if (diag) {
                    if (s     > t) e0 = 0.f;
                    if (s + 1 > t) e1 = 0.f;
                }
                rsum += e0 + e1;
                __half2 h = __floats2half2_rn(e0, e1);
                sm.S[rloc][wn * 16 + tn * 4 + fc] = *(uint32_t*)&h;
            }
            rsum += __shfl_xor_sync(0xffffffffu, rsum, 1);
            rsum += __shfl_xor_sync(0xffffffffu, rsum, 2);
            if (fc == 0) rs[rloc][wn] = rsum;
        }
    __syncthreads();

    if (tid < 128) {
        float v = rs[tid][0] + rs[tid][1] + rs[tid][2] + rs[tid][3];
        g_RS[((size_t)z * T + t0 + tid) * 16 + st] = v;
    }

    const int rr0 = tid >> 4;
    const int cw  = (tid & 15) * 4;
#pragma unroll
    for (int i = 0; i < 8; i++) {
        const int rr = rr0 + i * 16;
        uint4 v = *(const uint4*)&sm.S[rr][cw];
        *(uint4*)&Wp[(size_t)(t0 + rr) * T + s0 + cw * 2] = v;
    }
}

// ---------------------------------------------------------------------------
// Kernel 4: PAIRED streaming mean-of-softmax. One 384-thread block handles
// rows (T-1-j) [long, threads 0-255] and (j) [short, threads 256-383] of the
// same batch; combined valid length is constant (2050) -> perfectly balanced.
// Short-row threads also zero-fill columns [1024, 2048).
// grid = B*T/2.
// ---------------------------------------------------------------------------
__global__ void __launch_bounds__(384)
softmax_mean_kernel(float* __restrict__ out_mean)
{
    const int bb = blockIdx.x >> 10;        // batch (1024 pairs per batch)
    const int j  = blockIdx.x & 1023;
    const int tid = threadIdx.x;

    // row/thread assignment
    const bool longrow = (tid < 256);
    const int t  = longrow ? (T - 1 - j) : j;
    const int lt = longrow ? tid : (tid - 256);
    const int row = bb * T + t;

    const int nst = (t >> 7) + 1;
    const int L   = nst * 128;

    __shared__ float sinv[2][NH];
    // threads 0..15 -> long row sums; 256..271 -> short row sums
    if (lt < NH && (tid < 16 || (tid >= 256 && tid < 272))) {
        const int side = longrow ? 0 : 1;
        const float* p = g_RS + ((size_t)(lt * B + bb) * T + t) * 16;
        float s = 0.f;
        for (int i = 0; i < nst; i++) s += p[i];
        sinv[side][lt] = (1.0f / NH) / s;
    }
    __syncthreads();

    const int side = longrow ? 0 : 1;
    const int c0 = lt * 8;
    float acc[8];
#pragma unroll
    for (int i = 0; i < 8; i++) acc[i] = 0.f;

    if (c0 < L) {
        const size_t rowoff = ((size_t)row) * T + c0;
#pragma unroll
        for (int n = 0; n < NH; n++) {
            const __half* p = g_Wh + (size_t)n * (B * (size_t)T * T) + rowoff;
            uint4 u = *(const uint4*)p;
            const float w = sinv[side][n];
            float2 f;
            f = __half22float2(*(__half2*)&u.x); acc[0] += f.x * w; acc[1] += f.y * w;
            f = __half22float2(*((__half2*)&u.x + 1)); acc[2] += f.x * w; acc[3] += f.y * w;
            f = __half22float2(*(__half2*)&u.z); acc[4] += f.x * w; acc[5] += f.y * w;
            f = __half22float2(*((__half2*)&u.z + 1)); acc[6] += f.x * w; acc[7] += f.y * w;
        }
    }

    float* mrow = out_mean + (size_t)row * T;
    *(float4*)&mrow[c0]     = make_float4(acc[0], acc[1], acc[2], acc[3]);
    *(float4*)&mrow[c0 + 4] = make_float4(acc[4], acc[5], acc[6], acc[7]);

    uint4 hq;
    __half2 h;
    h = __floats2half2_rn(acc[0], acc[1]); hq.x = *(uint32_t*)&h;
    h = __floats2half2_rn(acc[2], acc[3]); hq.y = *(uint32_t*)&h;
    h = __floats2half2_rn(acc[4], acc[5]); hq.z = *(uint32_t*)&h;
    h = __floats2half2_rn(acc[6], acc[7]); hq.w = *(uint32_t*)&h;
    *(uint4*)&g_MWh[(size_t)row * T + c0] = hq;

    // short row covers only cols [0,1024); zero-fill [1024, 2048)
    if (!longrow) {
        const int c1 = c0 + 1024;
        const float4 z4 = make_float4(0.f, 0.f, 0.f, 0.f);
        *(float4*)&mrow[c1]     = z4;
        *(float4*)&mrow[c1 + 4] = z4;
        const uint4 zu = make_uint4(0u, 0u, 0u, 0u);
        *(uint4*)&g_MWh[(size_t)row * T + c1] = zu;
    }
}

// ---------------------------------------------------------------------------
// Kernel 5: AV via fp16 mma + ldmatrix, 16 s-chunks (EXACT R14).
// grid = (16, B, 16).
// ---------------------------------------------------------------------------
__global__ void __launch_bounds__(256)
av_fp16()
{
    const int tt    = blockIdx.x;
    const int b     = blockIdx.y;
    const int chunk = blockIdx.z;
    const int t0 = tt * 128;

    const int st_begin = chunk * 2;
    const int st_end   = min(chunk * 2 + 2, ((t0 + 127) >> 6) + 1);

    __shared__ __align__(16) uint32_t Aw[128][36];
    __shared__ __align__(16) uint32_t Bw[64][36];

    const int tid  = threadIdx.x;
    const int lane = tid & 31;
    const int wid  = tid >> 5;
    const int wm   = wid >> 1;
    const int wn   = wid & 1;
    const int fr   = lane >> 2;
    const int fc   = lane & 3;

    const int asr = tid >> 1;
    const int asc = (tid & 1) * 32;
    const int bsr = tid >> 2;
    const int bsc = (tid & 3) * 16;

    uint32_t aAddr[2];
    {
        const int lr = lane & 15, lk = (lane >> 4) * 4;
#pragma unroll
        for (int tm = 0; tm < 2; tm++)
            aAddr[tm] = smem_u32(&Aw[wm * 32 + tm * 16 + lr][lk]);
    }
    uint32_t bAddr[2];
    {
        const int br = (lane >> 4) * 8 + (lane & 7);
        const int bk = ((lane >> 3) & 1) * 4;
#pragma unroll
        for (int tp = 0; tp < 2; tp++)
            bAddr[tp] = smem_u32(&Bw[wn * 32 + tp * 16 + br][bk]);
    }

    float acc[2][4][4];
#pragma unroll
    for (int i = 0; i < 2; i++)
#pragma unroll
        for (int j = 0; j < 4; j++)
#pragma unroll
            for (int q = 0; q < 4; q++) acc[i][j][q] = 0.f;

    for (int st = st_begin; st < st_end; st++) {
        const int s0 = st * 64;
        if (st > st_begin) __syncthreads();
        {
            const __half* src = g_MWh + ((size_t)b * T + t0 + asr) * T + s0 + asc;
#pragma unroll
            for (int u = 0; u < 4; u++)
                *(uint4*)&Aw[asr][asc / 2 + u * 4] = *(const uint4*)&src[u * 8];
        }
        {
            const __half* src = g_Vth + ((size_t)b * D + bsr) * T + s0 + bsc;
#pragma unroll
            for (int u = 0; u < 2; u++)
                *(uint4*)&Bw[bsr][bsc / 2 + u * 4] = *(const uint4*)&src[u * 8];
        }
        __syncthreads();

#pragma unroll
        for (int ks = 0; ks < 4; ks++) {
            uint32_t af[2][4], bq0[4], bq1[4];
#pragma unroll
            for (int tm = 0; tm < 2; tm++)
                ldsm_x4(af[tm], aAddr[tm] + ks * 32);
            ldsm_x4(bq0, bAddr[0] + ks * 32);
            ldsm_x4(bq1, bAddr[1] + ks * 32);
            uint32_t bf[4][2];
            bf[0][0] = bq0[0]; bf[0][1] = bq0[1];
            bf[1][0] = bq0[2]; bf[1][1] = bq0[3];
            bf[2][0] = bq1[0]; bf[2][1] = bq1[1];
            bf[3][0] = bq1[2]; bf[3][1] = bq1[3];
#pragma unroll
            for (int tm = 0; tm < 2; tm++)
#pragma unroll
                for (int tn = 0; tn < 4; tn++)
                    mma_fp16(acc[tm][tn], af[tm], bf[tn]);
        }
    }

    float* Cp = g_MHp + (size_t)chunk * B * T * D;
#pragma unroll
    for (int tm = 0; tm < 2; tm++)
#pragma unroll
        for (int tn = 0; tn < 4; tn++) {
            const int t = t0 + wm * 32 + tm * 16 + fr;
            const int d = wn * 32 + tn * 8 + 2 * fc;
            float2 o;
            o.x = acc[tm][tn][0]; o.y = acc[tm][tn][1];
            *(float2*)&Cp[((size_t)b * T + t) * D + d] = o;
            o.x = acc[tm][tn][2]; o.y = acc[tm][tn][3];
            *(float2*)&Cp[((size_t)b * T + t + 8) * D + d] = o;
        }
}

// mhsum: g_MH = sum of NAVCH AV partials (fixed order). grid = B*T*D/256.
__global__ void mhsum_kernel()
{
    const size_t i = (size_t)blockIdx.x * 256 + threadIdx.x;
    const size_t N = (size_t)B * T * D;
    float v = 0.f;
#pragma unroll
    for (int p = 0; p < NAVCH; p++) v += g_MHp[p * N + i];
    g_MH[i] = v;
}

// ---------------------------------------------------------------------------
// Kernel 6: out = g_MH @ Wo + bo. grid = (H/64, B*T/64).
// ---------------------------------------------------------------------------
__global__ void out_kernel(const float* __restrict__ Wo,
                           const float* __restrict__ bo,
                           float* __restrict__ out)
{
    const int n0 = blockIdx.x * 64;
    const int m0 = blockIdx.y * 64;

    __shared__ float As[64][65];
    __shared__ float Bs[64][65];

    const int tx = threadIdx.x, ty = threadIdx.y;
    const int tid = ty * 16 + tx;

#pragma unroll
    for (int i = 0; i < 16; i++) {
        int idx = tid + i * 256;
        int r = idx >> 6, c = idx & 63;
        As[r][c] = g_MH[(size_t)(m0 + r) * D + c];
        Bs[r][c] = Wo[(size_t)r * H + n0 + c];
    }
    __syncthreads();

    float acc[4][4];
#pragma unroll
    for (int i = 0; i < 4; i++)
#pragma unroll
        for (int j = 0; j < 4; j++) acc[i][j] = 0.f;

#pragma unroll 8
    for (int kk = 0; kk < 64; kk++) {
        float a[4], bb[4];
#pragma unroll
        for (int i = 0; i < 4; i++) a[i]  = As[ty * 4 + i][kk];
#pragma unroll
        for (int j = 0; j < 4; j++) bb[j] = Bs[kk][tx * 4 + j];
#pragma unroll
        for (int i = 0; i < 4; i++)
#pragma unroll
            for (int j = 0; j < 4; j++) acc[i][j] += a[i] * bb[j];
    }

#pragma unroll
    for (int i = 0; i < 4; i++)
#pragma unroll
        for (int j = 0; j < 4; j++)
            out[(size_t)(m0 + ty * 4 + i) * H + n0 + tx * 4 + j] =
                acc[i][j] + bo[n0 + tx * 4 + j];
}

// ---------------------------------------------------------------------------
extern "C" void kernel_launch(void* const* d_in, const int* in_sizes, int n_in,
                              void* d_out, int out_size)
{
    const float* x  = (const float*)d_in[0];
    const float* Wq = (const float*)d_in[1];
    const float* bq = (const float*)d_in[2];
    const float* Wk = (const float*)d_in[3];
    const float* bk = (const float*)d_in[4];
    const float* Wv = (const float*)d_in[5];
    const float* bv = (const float*)d_in[6];
    const float* Wo = (const float*)d_in[7];
    const float* bo = (const float*)d_in[8];

    float* out      = (float*)d_out;                 // [B,T,H]
    float* mean_out = out + (size_t)B * T * H;       // [B,T,T]

    dim3 blk16(16, 16);

    static cudaStream_t s_v = nullptr;
    static cudaEvent_t  ev_fork = nullptr, ev_join = nullptr;
    if (s_v == nullptr) {
        cudaStreamCreateWithFlags(&s_v, cudaStreamNonBlocking);
        cudaEventCreateWithFlags(&ev_fork, cudaEventDisableTiming);
        cudaEventCreateWithFlags(&ev_join, cudaEventDisableTiming);
    }

    cudaEventRecord(ev_fork, 0);
    cudaStreamWaitEvent(s_v, ev_fork, 0);
    vproj_kernel <<<dim3((B * T) / 64, 4), blk16, 0, s_v>>>(x, Wv);
    vtsum_kernel <<<(B * T) / 64, 256, 0, s_v>>>(bv);
    cudaEventRecord(ev_join, s_v);

    qkproj_bf16        <<<dim3(H / 128, (B * T) / 128, 2), 256>>>(x, Wq, bq, Wk, bk);
    scores_bf16        <<<dim3(T / 128, T / 128, NH * B), 256>>>();
    softmax_mean_kernel<<<(B * T) / 2, 384>>>(mean_out);

    cudaStreamWaitEvent(0, ev_join, 0);
    av_fp16            <<<dim3(T / 128, B, NAVCH), 256>>>();
    mhsum_kernel       <<<(B * T * D) / 256, 256>>>();
    out_kernel         <<<dim3(H / 64, (B * T) / 64), blk16>>>(Wo, bo, out);
}